// round 9
// baseline (speedup 1.0000x reference)
#include <cuda_runtime.h>
#include <math.h>

// Dims (fixed): B=64, T=256, S=256, E=256, H=1024
#define DB 64
#define DT 256
#define DS 256
#define DE 256
#define DH 1024

// ---- static scratch ----
__device__ float g_xgates[(size_t)DB * DT * 4 * DH]; // [B*T, 4H]
__device__ float g_projkey[(size_t)DB * DS * DH];    // [B*S, H]
__device__ float g_q[(size_t)DB * DT * DH];          // [B*T, H]
__device__ float g_probs[(size_t)DB * DT * DS];      // [B*T, S]
__device__ float g_ctx[(size_t)DB * DT * 2 * DH];    // [B*T, 2H]
__device__ float g_h0[DB * DH];
__device__ float g_c[DB * DH];

__device__ __forceinline__ float tanh_f(float x) {
    float e = __expf(2.0f * x);
    return 1.0f - __fdividef(2.0f, e + 1.0f);
}
__device__ __forceinline__ float sigmoid_f(float x) {
    return __fdividef(1.0f, 1.0f + __expf(-x));
}

// split x into tf32 hi + tf32 lo (stored as f32 bit patterns)
__device__ __forceinline__ void tf32_split(float x, float& hi, float& lo) {
    unsigned hu, lu;
    asm("cvt.rna.tf32.f32 %0, %1;" : "=r"(hu) : "f"(x));
    float hf = __uint_as_float(hu);
    float r = x - hf;
    asm("cvt.rna.tf32.f32 %0, %1;" : "=r"(lu) : "f"(r));
    hi = hf;
    lo = __uint_as_float(lu);
}

#define MMA_TF32(d, a0, a1, a2, a3, b0, b1)                                   \
    asm volatile(                                                             \
        "mma.sync.aligned.m16n8k8.row.col.f32.tf32.tf32.f32 "                 \
        "{%0,%1,%2,%3}, {%4,%5,%6,%7}, {%8,%9}, {%0,%1,%2,%3};"               \
        : "+f"(d[0]), "+f"(d[1]), "+f"(d[2]), "+f"(d[3])                      \
        : "r"(__float_as_uint(a0)), "r"(__float_as_uint(a1)),                 \
          "r"(__float_as_uint(a2)), "r"(__float_as_uint(a3)),                 \
          "r"(__float_as_uint(b0)), "r"(__float_as_uint(b1)))

// ======================================================================
// TF32 tensor-core GEMM with 3xTF32 split (fp32-level accuracy).
// Block tile 128x128, BK=16, 256 threads (8 warps, 2x4), warp tile 64x32.
// ======================================================================
template <bool B_TRANS>
__global__ __launch_bounds__(256, 2) void gemm_tf32(
    int M, int N, int K,
    const float* __restrict__ A, int lda, long long sA,
    const float* __restrict__ Bm, int ldb, long long sB,
    float* __restrict__ C, int ldc, long long sC,
    const float* __restrict__ bias, int accumulate)
{
    extern __shared__ float sm[];
    float* Ahi = sm;
    float* Alo = sm + 4352;
    float* Bhi = sm + 8704;
    float* Blo = sm + 13056;

    const int bz = blockIdx.z;
    A += (long long)bz * sA;
    Bm += (long long)bz * sB;
    C += (long long)bz * sC;

    const int m0 = blockIdx.y * 128, n0 = blockIdx.x * 128;
    const int tid = threadIdx.x;
    const int wid = tid >> 5, lane = tid & 31;
    const int warp_m = wid >> 2, warp_n = wid & 3;
    const int tg = lane & 3, gr = lane >> 2;

    const int ar = tid >> 1;
    const int ac = (tid & 1) * 8;
    const float* Ag = A + (long long)(m0 + ar) * lda + ac;
    const float* Bg;
    int bkr = 0, bnc = 0;
    if (B_TRANS) {
        Bg = Bm + (long long)(n0 + ar) * ldb + ac;
    } else {
        bkr = tid >> 4;
        bnc = (tid & 15) * 8;
        Bg = Bm + (long long)bkr * ldb + n0 + bnc;
    }

    float acc[4][4][4];
#pragma unroll
    for (int i = 0; i < 4; i++)
#pragma unroll
        for (int j = 0; j < 4; j++)
#pragma unroll
            for (int c = 0; c < 4; c++) acc[i][j][c] = 0.0f;

    const int nk = K >> 4;
    float4 a0v, a1v, b0v, b1v;

    a0v = *(const float4*)Ag;
    a1v = *(const float4*)(Ag + 4);
    b0v = *(const float4*)Bg;
    b1v = *(const float4*)(Bg + 4);

#define STORE_TILES(BUF)                                                      \
    {                                                                         \
        float va[8] = {a0v.x, a0v.y, a0v.z, a0v.w, a1v.x, a1v.y, a1v.z, a1v.w}; \
        _Pragma("unroll")                                                     \
        for (int j = 0; j < 8; j++) {                                         \
            float h, l;                                                       \
            tf32_split(va[j], h, l);                                          \
            Ahi[(BUF) * 2176 + (ac + j) * 136 + ar] = h;                      \
            Alo[(BUF) * 2176 + (ac + j) * 136 + ar] = l;                      \
        }                                                                     \
        if (B_TRANS) {                                                        \
            float vb[8] = {b0v.x, b0v.y, b0v.z, b0v.w, b1v.x, b1v.y, b1v.z, b1v.w}; \
            _Pragma("unroll")                                                 \
            for (int j = 0; j < 8; j++) {                                     \
                float h, l;                                                   \
                tf32_split(vb[j], h, l);                                      \
                Bhi[(BUF) * 2176 + (ac + j) * 136 + ar] = h;                  \
                Blo[(BUF) * 2176 + (ac + j) * 136 + ar] = l;                  \
            }                                                                 \
        } else {                                                              \
            float vb[8] = {b0v.x, b0v.y, b0v.z, b0v.w, b1v.x, b1v.y, b1v.z, b1v.w}; \
            float hh[8], ll[8];                                               \
            _Pragma("unroll")                                                 \
            for (int j = 0; j < 8; j++) tf32_split(vb[j], hh[j], ll[j]);      \
            float4 h0 = make_float4(hh[0], hh[1], hh[2], hh[3]);              \
            float4 h1 = make_float4(hh[4], hh[5], hh[6], hh[7]);              \
            float4 l0 = make_float4(ll[0], ll[1], ll[2], ll[3]);              \
            float4 l1 = make_float4(ll[4], ll[5], ll[6], ll[7]);              \
            *(float4*)&Bhi[(BUF) * 2176 + bkr * 136 + bnc] = h0;              \
            *(float4*)&Bhi[(BUF) * 2176 + bkr * 136 + bnc + 4] = h1;          \
            *(float4*)&Blo[(BUF) * 2176 + bkr * 136 + bnc] = l0;              \
            *(float4*)&Blo[(BUF) * 2176 + bkr * 136 + bnc + 4] = l1;          \
        }                                                                     \
    }

    STORE_TILES(0);
    __syncthreads();

    int p = 0;
    for (int kt = 0; kt < nk; ++kt) {
        if (kt + 1 < nk) {
            const float* Agn = Ag + (long long)(kt + 1) * 16;
            a0v = *(const float4*)Agn;
            a1v = *(const float4*)(Agn + 4);
            const float* Bgn = B_TRANS ? (Bg + (long long)(kt + 1) * 16)
                                       : (Bg + (long long)(kt + 1) * 16 * ldb);
            b0v = *(const float4*)Bgn;
            b1v = *(const float4*)(Bgn + 4);
        }

        const int base = p * 2176;
#pragma unroll
        for (int s = 0; s < 2; ++s) {
            const int k0 = s * 8;
            float bh[4][2], bl[4][2];
#pragma unroll
            for (int nt = 0; nt < 4; nt++) {
                int nc = warp_n * 32 + nt * 8 + gr;
                bh[nt][0] = Bhi[base + (k0 + tg) * 136 + nc];
                bh[nt][1] = Bhi[base + (k0 + tg + 4) * 136 + nc];
                bl[nt][0] = Blo[base + (k0 + tg) * 136 + nc];
                bl[nt][1] = Blo[base + (k0 + tg + 4) * 136 + nc];
            }
#pragma unroll
            for (int mt = 0; mt < 4; mt++) {
                int mr = warp_m * 64 + mt * 16 + gr;
                float ah0 = Ahi[base + (k0 + tg) * 136 + mr];
                float ah1 = Ahi[base + (k0 + tg) * 136 + mr + 8];
                float ah2 = Ahi[base + (k0 + tg + 4) * 136 + mr];
                float ah3 = Ahi[base + (k0 + tg + 4) * 136 + mr + 8];
                float al0 = Alo[base + (k0 + tg) * 136 + mr];
                float al1 = Alo[base + (k0 + tg) * 136 + mr + 8];
                float al2 = Alo[base + (k0 + tg + 4) * 136 + mr];
                float al3 = Alo[base + (k0 + tg + 4) * 136 + mr + 8];
#pragma unroll
                for (int nt = 0; nt < 4; nt++) {
                    MMA_TF32(acc[mt][nt], ah0, ah1, ah2, ah3, bh[nt][0], bh[nt][1]);
                    MMA_TF32(acc[mt][nt], ah0, ah1, ah2, ah3, bl[nt][0], bl[nt][1]);
                    MMA_TF32(acc[mt][nt], al0, al1, al2, al3, bh[nt][0], bh[nt][1]);
                }
            }
        }

        if (kt + 1 < nk) STORE_TILES(p ^ 1);
        __syncthreads();
        p ^= 1;
    }
#undef STORE_TILES

#pragma unroll
    for (int mt = 0; mt < 4; mt++) {
        int gm0 = m0 + warp_m * 64 + mt * 16 + gr;
#pragma unroll
        for (int nt = 0; nt < 4; nt++) {
            int gn = n0 + warp_n * 32 + nt * 8 + tg * 2;
            float2 v0 = make_float2(acc[mt][nt][0], acc[mt][nt][1]);
            float2 v1 = make_float2(acc[mt][nt][2], acc[mt][nt][3]);
            if (bias) {
                float2 bb = *(const float2*)&bias[gn];
                v0.x += bb.x; v0.y += bb.y;
                v1.x += bb.x; v1.y += bb.y;
            }
            float* c0p = C + (long long)gm0 * ldc + gn;
            float* c1p = c0p + 8 * (long long)ldc;
            if (accumulate) {
                float2 o0 = *(const float2*)c0p;
                float2 o1 = *(const float2*)c1p;
                v0.x += o0.x; v0.y += o0.y;
                v1.x += o1.x; v1.y += o1.y;
            }
            *(float2*)c0p = v0;
            *(float2*)c1p = v1;
        }
    }
}

// ======================================================================
// Fused LSTM step: gates = hprev @ Wsub^T (TF32x3 mma) + cell, one kernel.
// grid = 128 blocks; block bi owns h-indices [bi*8, bi*8+8) for all 4 gates
// (32 W rows: gate g row = g*1024 + h). Tile M=64(batch) N=32 K=1024, BK=16.
// 8 warps: warp_m (2) x warp_n (4); warp tile 32x8 = 2 m16 tiles x 1 n8.
// ======================================================================
__global__ __launch_bounds__(256) void lstm_step(
    const float* __restrict__ hprev, int lda,
    const float* __restrict__ W,      // W_hh [4096,1024]
    const float* __restrict__ xg_t,   // x_gates + t*4096
    float* __restrict__ c,            // [B,H]
    float* __restrict__ hout)         // hseq + t*DH
{
    __shared__ float Ahi[2][16][68], Alo[2][16][68];
    __shared__ float Bhi[2][16][36], Blo[2][16][36];
    __shared__ float Gs[64][33];

    const int h0 = blockIdx.x * 8;
    const int tid = threadIdx.x;
    const int wid = tid >> 5, lane = tid & 31;
    const int warp_m = wid >> 2, warp_n = wid & 3;
    const int tg = lane & 3, gr = lane >> 2;

    const int ar = tid >> 2;          // 0..63
    const int ac = (tid & 3) * 4;     // 0,4,8,12
    const float* Ag = hprev + (long long)ar * lda + ac;
    const int br = (tid >> 2) & 31;   // 0..31
    const int wrow = (br >> 3) * 1024 + h0 + (br & 7);
    const float* Bg = W + (long long)wrow * DH + ac;
    const bool bload = (tid < 128);

    float acc[2][4];
#pragma unroll
    for (int i = 0; i < 2; i++)
#pragma unroll
        for (int j = 0; j < 4; j++) acc[i][j] = 0.0f;

    const int nk = DH / 16; // 64
    float4 av = *(const float4*)Ag;
    float4 bv = bload ? *(const float4*)Bg : make_float4(0, 0, 0, 0);

#define LS_STORE(BUF)                                                         \
    {                                                                         \
        float va[4] = {av.x, av.y, av.z, av.w};                               \
        _Pragma("unroll")                                                     \
        for (int j = 0; j < 4; j++) {                                         \
            float h, l;                                                       \
            tf32_split(va[j], h, l);                                          \
            Ahi[BUF][ac + j][ar] = h;                                         \
            Alo[BUF][ac + j][ar] = l;                                         \
        }                                                                     \
        if (bload) {                                                          \
            float vb[4] = {bv.x, bv.y, bv.z, bv.w};                           \
            _Pragma("unroll")                                                 \
            for (int j = 0; j < 4; j++) {                                     \
                float h, l;                                                   \
                tf32_split(vb[j], h, l);                                      \
                Bhi[BUF][ac + j][br] = h;                                     \
                Blo[BUF][ac + j][br] = l;                                     \
            }                                                                 \
        }                                                                     \
    }

    LS_STORE(0);
    __syncthreads();

    int p = 0;
    for (int kt = 0; kt < nk; ++kt) {
        if (kt + 1 < nk) {
            av = *(const float4*)(Ag + (kt + 1) * 16);
            if (bload) bv = *(const float4*)(Bg + (kt + 1) * 16);
        }
#pragma unroll
        for (int s = 0; s < 2; ++s) {
            const int k0 = s * 8;
            const int nc = warp_n * 8 + gr;
            float b0h = Bhi[p][k0 + tg][nc];
            float b1h = Bhi[p][k0 + tg + 4][nc];
            float b0l = Blo[p][k0 + tg][nc];
            float b1l = Blo[p][k0 + tg + 4][nc];
#pragma unroll
            for (int mt = 0; mt < 2; mt++) {
                int mr = warp_m * 32 + mt * 16 + gr;
                float ah0 = Ahi[p][k0 + tg][mr];
                float ah1 = Ahi[p][k0 + tg][mr + 8];
                float ah2 = Ahi[p][k0 + tg + 4][mr];
                float ah3 = Ahi[p][k0 + tg + 4][mr + 8];
                float al0 = Alo[p][k0 + tg][mr];
                float al1 = Alo[p][k0 + tg][mr + 8];
                float al2 = Alo[p][k0 + tg + 4][mr];
                float al3 = Alo[p][k0 + tg + 4][mr + 8];
                MMA_TF32(acc[mt], ah0, ah1, ah2, ah3, b0h, b1h);
                MMA_TF32(acc[mt], ah0, ah1, ah2, ah3, b0l, b1l);
                MMA_TF32(acc[mt], al0, al1, al2, al3, b0h, b1h);
            }
        }
        if (kt + 1 < nk) LS_STORE(p ^ 1);
        __syncthreads();
        p ^= 1;
    }
#undef LS_STORE

    // write gate accumulators to smem
#pragma unroll
    for (int mt = 0; mt < 2; mt++) {
        int r0 = warp_m * 32 + mt * 16 + gr;
        int cc = warp_n * 8 + tg * 2;
        Gs[r0][cc] = acc[mt][0];
        Gs[r0][cc + 1] = acc[mt][1];
        Gs[r0 + 8][cc] = acc[mt][2];
        Gs[r0 + 8][cc + 1] = acc[mt][3];
    }
    __syncthreads();

    // pointwise cell: 512 outputs (64 b x 8 h), 2 per thread
#pragma unroll
    for (int j = 0; j < 2; j++) {
        int o = tid + j * 256;
        int b = o >> 3, hoff = o & 7;
        int h = h0 + hoff;
        const float* xg = xg_t + (long long)b * (DT * 4 * DH);
        float ig = Gs[b][hoff] + xg[h];
        float fg = Gs[b][8 + hoff] + xg[1024 + h];
        float gg = Gs[b][16 + hoff] + xg[2048 + h];
        float og = Gs[b][24 + hoff] + xg[3072 + h];
        float cv = sigmoid_f(fg) * c[b * DH + h] + sigmoid_f(ig) * tanh_f(gg);
        c[b * DH + h] = cv;
        hout[(long long)b * (DT * DH) + h] = sigmoid_f(og) * tanh_f(cv);
    }
}

// ======================================================================
// Small generic GEMM (bridge only): C = tanh(A*B^T + bias)
// ======================================================================
template <int TM, int TN>
__global__ __launch_bounds__(256) void gemm_small(
    int M, int N, int K,
    const float* __restrict__ A, int lda,
    const float* __restrict__ Bm, int ldb,
    float* __restrict__ C, int ldc,
    const float* __restrict__ bias)
{
    constexpr int BM = 16 * TM, BN = 16 * TN, BK = 16;
    __shared__ float As[BK][BM + 4];
    __shared__ float Bs[BK][BN + 4];
    int m0 = blockIdx.y * BM, n0 = blockIdx.x * BN;
    int tid = threadIdx.x;
    int rm = (tid / 16) * TM, rn = (tid % 16) * TN;
    float acc[TM][TN];
#pragma unroll
    for (int i = 0; i < TM; i++)
#pragma unroll
        for (int j = 0; j < TN; j++) acc[i][j] = 0.0f;
    for (int k0 = 0; k0 < K; k0 += BK) {
        for (int i = tid; i < BM * BK; i += 256) {
            int kk = i % BK, m = i / BK;
            int gm = m0 + m, gk = k0 + kk;
            As[kk][m] = (gm < M) ? A[(long long)gm * lda + gk] : 0.0f;
        }
        for (int i = tid; i < BN * BK; i += 256) {
            int kk = i % BK, n = i / BK;
            int gn = n0 + n, gk = k0 + kk;
            Bs[kk][n] = (gn < N) ? Bm[(long long)gn * ldb + gk] : 0.0f;
        }
        __syncthreads();
#pragma unroll
        for (int kk = 0; kk < BK; kk++) {
            float a[TM], bb[TN];
#pragma unroll
            for (int i = 0; i < TM; i++) a[i] = As[kk][rm + i];
#pragma unroll
            for (int j = 0; j < TN; j++) bb[j] = Bs[kk][rn + j];
#pragma unroll
            for (int i = 0; i < TM; i++)
#pragma unroll
                for (int j = 0; j < TN; j++) acc[i][j] += a[i] * bb[j];
        }
        __syncthreads();
    }
#pragma unroll
    for (int i = 0; i < TM; i++) {
        int gm = m0 + rm + i;
        if (gm >= M) continue;
#pragma unroll
        for (int j = 0; j < TN; j++) {
            int gn = n0 + rn + j;
            if (gn >= N) continue;
            C[(long long)gm * ldc + gn] = tanh_f(acc[i][j] + bias[gn]);
        }
    }
}

// energy[b,t,s] = sum_h tanh(q[b,t,h] + pk[b,s,h]) * v[h]  (mask all-true)
__global__ __launch_bounds__(256) void energy_kernel(
    const float* __restrict__ q, const float* __restrict__ pk,
    const float* __restrict__ v, float* __restrict__ out)
{
    int b = blockIdx.z;
    int t0 = blockIdx.y * 32, s0 = blockIdx.x * 32;
    __shared__ float Qs[32][33], Ps[32][33], Vs[32];
    int tid = threadIdx.x;
    int hh = tid & 31, r = tid >> 5;
    int tr = (tid / 16) * 2, sc = (tid % 16) * 2;
    const float* qb = q + ((long long)b * DT + t0) * DH;
    const float* pb = pk + ((long long)b * DS + s0) * DH;
    float a00 = 0, a01 = 0, a10 = 0, a11 = 0;

    for (int h0 = 0; h0 < DH; h0 += 32) {
#pragma unroll
        for (int rr = 0; rr < 4; rr++) {
            int row = r + rr * 8;
            Qs[hh][row] = qb[(long long)row * DH + h0 + hh];
            Ps[hh][row] = pb[(long long)row * DH + h0 + hh];
        }
        if (tid < 32) Vs[tid] = v[h0 + tid];
        __syncthreads();
#pragma unroll 8
        for (int k = 0; k < 32; k++) {
            float vv = Vs[k];
            float q0 = Qs[k][tr], q1 = Qs[k][tr + 1];
            float p0 = Ps[k][sc], p1 = Ps[k][sc + 1];
            a00 += tanh_f(q0 + p0) * vv;
            a01 += tanh_f(q0 + p1) * vv;
            a10 += tanh_f(q1 + p0) * vv;
            a11 += tanh_f(q1 + p1) * vv;
        }
        __syncthreads();
    }
    float* o0 = out + ((long long)b * DT + t0 + tr) * DS + s0 + sc;
    float* o1 = o0 + DS;
    o0[0] = a00; o0[1] = a01;
    o1[0] = a10; o1[1] = a11;
}

__global__ __launch_bounds__(256) void softmax_kernel(float* __restrict__ p)
{
    int row = blockIdx.x * 8 + (threadIdx.x >> 5);
    int lane = threadIdx.x & 31;
    float* pr = p + (long long)row * DS;
    float vals[8];
    float mx = -3.0e38f;
#pragma unroll
    for (int j = 0; j < 8; j++) { vals[j] = pr[lane + j * 32]; mx = fmaxf(mx, vals[j]); }
#pragma unroll
    for (int o = 16; o > 0; o >>= 1) mx = fmaxf(mx, __shfl_xor_sync(0xFFFFFFFFu, mx, o));
    float sum = 0.0f;
#pragma unroll
    for (int j = 0; j < 8; j++) { vals[j] = __expf(vals[j] - mx); sum += vals[j]; }
#pragma unroll
    for (int o = 16; o > 0; o >>= 1) sum += __shfl_xor_sync(0xFFFFFFFFu, sum, o);
    float inv = __fdividef(1.0f, sum);
#pragma unroll
    for (int j = 0; j < 8; j++) pr[lane + j * 32] = vals[j] * inv;
}

__global__ __launch_bounds__(256) void copy_hfinal(
    const float* __restrict__ hseq, float* __restrict__ out)
{
    int idx = blockIdx.x * 256 + threadIdx.x;
    int b = idx >> 10, h = idx & 1023;
    out[idx] = hseq[((long long)b * DT + (DT - 1)) * DH + h];
}

// ======================================================================
extern "C" void kernel_launch(void* const* d_in, const int* in_sizes, int n_in,
                              void* d_out, int out_size)
{
    const float* trg      = (const float*)d_in[0];
    const float* enc      = (const float*)d_in[1];
    const float* ehf      = (const float*)d_in[2];
    const float* ecf      = (const float*)d_in[3];
    const float* W_ih     = (const float*)d_in[6];
    const float* W_hh     = (const float*)d_in[7];
    const float* b_lstm   = (const float*)d_in[8];
    const float* W_bridge = (const float*)d_in[9];
    const float* b_bridge = (const float*)d_in[10];
    const float* W_key    = (const float*)d_in[11];
    const float* W_query  = (const float*)d_in[12];
    const float* v_energy = (const float*)d_in[13];
    const float* W_pre    = (const float*)d_in[14];

    float* out  = (float*)d_out;
    float* hseq = out;
    float* hfin = out + (long long)DB * DT * DH;
    float* pre  = hfin + (long long)DB * DH;

    float *p_xg, *p_pk, *p_q, *p_probs, *p_ctx, *p_h0, *p_c;
    cudaGetSymbolAddress((void**)&p_xg, g_xgates);
    cudaGetSymbolAddress((void**)&p_pk, g_projkey);
    cudaGetSymbolAddress((void**)&p_q, g_q);
    cudaGetSymbolAddress((void**)&p_probs, g_probs);
    cudaGetSymbolAddress((void**)&p_ctx, g_ctx);
    cudaGetSymbolAddress((void**)&p_h0, g_h0);
    cudaGetSymbolAddress((void**)&p_c, g_c);

    const int BT = DB * DT; // 16384
    const int SMEM_TF = 69632;
    cudaFuncSetAttribute(gemm_tf32<true>,
                         cudaFuncAttributeMaxDynamicSharedMemorySize, SMEM_TF);
    cudaFuncSetAttribute(gemm_tf32<false>,
                         cudaFuncAttributeMaxDynamicSharedMemorySize, SMEM_TF);

    // Bridge
    gemm_small<4, 2><<<dim3(DH / 32, 1, 1), 256>>>(
        DB, DH, 2 * DH, ehf, 2 * DH, W_bridge, 2 * DH, p_h0, DH, b_bridge);
    gemm_small<4, 2><<<dim3(DH / 32, 1, 1), 256>>>(
        DB, DH, 2 * DH, ecf, 2 * DH, W_bridge, 2 * DH, p_c, DH, b_bridge);

    // x_gates = trg @ W_ih^T + b_lstm : [16384, 4096] K=256
    gemm_tf32<true><<<dim3(32, 128, 1), 256, SMEM_TF>>>(
        BT, 4 * DH, DE, trg, DE, 0, W_ih, DE, 0,
        p_xg, 4 * DH, 0, b_lstm, 0);

    // proj_key = enc @ W_key^T : [16384, 1024] K=2048
    gemm_tf32<true><<<dim3(8, 128, 1), 256, SMEM_TF>>>(
        BT, DH, 2 * DH, enc, 2 * DH, 0, W_key, 2 * DH, 0,
        p_pk, DH, 0, nullptr, 0);

    // Sequential LSTM: fused gate-GEMM (tensor cores) + cell per step
    for (int t = 0; t < DT; t++) {
        const float* hprev = (t == 0) ? p_h0 : (hseq + (long long)(t - 1) * DH);
        int lda = (t == 0) ? DH : (DT * DH);
        lstm_step<<<128, 256>>>(hprev, lda, W_hh,
                                p_xg + (long long)t * 4 * DH, p_c,
                                hseq + (long long)t * DH);
    }

    // q = h_seq @ W_query^T : [16384, 1024] K=1024
    gemm_tf32<true><<<dim3(8, 128, 1), 256, SMEM_TF>>>(
        BT, DH, DH, hseq, DH, 0, W_query, DH, 0,
        p_q, DH, 0, nullptr, 0);

    // energy + softmax
    energy_kernel<<<dim3(DS / 32, DT / 32, DB), 256>>>(p_q, p_pk, v_energy, p_probs);
    softmax_kernel<<<BT / 8, 256>>>(p_probs);

    // ctx[b] = probs[b] @ enc[b] : batched NN [256,256]x[256,2048]
    gemm_tf32<false><<<dim3(16, 2, DB), 256, SMEM_TF>>>(
        DT, 2 * DH, DS,
        p_probs, DS, (long long)DT * DS,
        enc, 2 * DH, (long long)DS * 2 * DH,
        p_ctx, 2 * DH, (long long)DT * 2 * DH, nullptr, 0);

    // pre = [trg | h_seq | ctx] @ W_pre^T : three accumulating GEMMs
    gemm_tf32<true><<<dim3(8, 128, 1), 256, SMEM_TF>>>(
        BT, DH, DE, trg, DE, 0, W_pre, 3328, 0,
        pre, DH, 0, nullptr, 0);
    gemm_tf32<true><<<dim3(8, 128, 1), 256, SMEM_TF>>>(
        BT, DH, DH, hseq, DH, 0, W_pre + DE, 3328, 0,
        pre, DH, 0, nullptr, 1);
    gemm_tf32<true><<<dim3(8, 128, 1), 256, SMEM_TF>>>(
        BT, DH, 2 * DH, p_ctx, 2 * DH, 0, W_pre + DE + DH, 3328, 0,
        pre, DH, 0, nullptr, 1);

    copy_hfinal<<<DB * DH / 256, 256>>>(hseq, hfin);
}

// round 10
// speedup vs baseline: 1.2355x; 1.2355x over previous
#include <cuda_runtime.h>
#include <cuda_bf16.h>
#include <math.h>

// Dims (fixed): B=64, T=256, S=256, E=256, H=1024
#define DB 64
#define DT 256
#define DS 256
#define DE 256
#define DH 1024

// ---- static scratch ----
__device__ float g_xgates[(size_t)DB * DT * 4 * DH]; // [B*T, 4H]
__device__ float g_projkey[(size_t)DB * DS * DH];    // [B*S, H]
__device__ float g_q[(size_t)DB * DT * DH];          // [B*T, H]
__device__ float g_probs[(size_t)DB * DT * DS];      // [B*T, S]
__device__ float g_ctx[(size_t)DB * DT * 2 * DH];    // [B*T, 2H]
__device__ float g_h0[DB * DH];
__device__ float g_c[DB * DH];
__device__ float g_gates[DB * 4 * DH];

__device__ __forceinline__ float tanh_f(float x) {
    float e = __expf(2.0f * x);
    return 1.0f - __fdividef(2.0f, e + 1.0f);
}
__device__ __forceinline__ float tanh_a(float x) {
    float y;
    asm("tanh.approx.f32 %0, %1;" : "=f"(y) : "f"(x));
    return y;
}
__device__ __forceinline__ float sigmoid_f(float x) {
    return __fdividef(1.0f, 1.0f + __expf(-x));
}

// split two floats into packed bf16x2 hi + lo words (elem0 in low half)
__device__ __forceinline__ void bf16_split2(float x0, float x1,
                                            unsigned& hi, unsigned& lo) {
    __nv_bfloat16 h0 = __float2bfloat16(x0), h1 = __float2bfloat16(x1);
    float r0 = x0 - __bfloat162float(h0);
    float r1 = x1 - __bfloat162float(h1);
    __nv_bfloat16 l0 = __float2bfloat16(r0), l1 = __float2bfloat16(r1);
    hi = ((unsigned)__bfloat16_as_ushort(h1) << 16) | __bfloat16_as_ushort(h0);
    lo = ((unsigned)__bfloat16_as_ushort(l1) << 16) | __bfloat16_as_ushort(l0);
}

#define MMA_BF16(d, a0, a1, a2, a3, b0, b1)                                   \
    asm volatile(                                                             \
        "mma.sync.aligned.m16n8k16.row.col.f32.bf16.bf16.f32 "                \
        "{%0,%1,%2,%3}, {%4,%5,%6,%7}, {%8,%9}, {%0,%1,%2,%3};"               \
        : "+f"(d[0]), "+f"(d[1]), "+f"(d[2]), "+f"(d[3])                      \
        : "r"(a0), "r"(a1), "r"(a2), "r"(a3), "r"(b0), "r"(b1))

// ======================================================================
// bf16x3-split tensor-core GEMM (near-fp32 accuracy).
// C = A[M,K]*B[N,K]^T (B_TRANS) or A[M,K]*B[K,N] (NN), + bias/accumulate.
// Block tile 128x128, BK=16, 256 threads (8 warps 2x4), warp tile 64x32.
// Requires M%128==0, N%128==0, K%16==0.
// ======================================================================
template <bool B_TRANS>
__global__ __launch_bounds__(256, 2) void gemm_bf16(
    int M, int N, int K,
    const float* __restrict__ A, int lda, long long sA,
    const float* __restrict__ Bm, int ldb, long long sB,
    float* __restrict__ C, int ldc, long long sC,
    const float* __restrict__ bias, int accumulate)
{
    // word arrays: [2 buf][8 k2][136]
    __shared__ unsigned Ahi[2 * 8 * 136], Alo[2 * 8 * 136];
    __shared__ unsigned Bhi[2 * 8 * 136], Blo[2 * 8 * 136];

    const int bz = blockIdx.z;
    A += (long long)bz * sA;
    Bm += (long long)bz * sB;
    C += (long long)bz * sC;

    const int m0 = blockIdx.y * 128, n0 = blockIdx.x * 128;
    const int tid = threadIdx.x;
    const int wid = tid >> 5, lane = tid & 31;
    const int warp_m = wid >> 2, warp_n = wid & 3;
    const int tg = lane & 3, gr = lane >> 2;

    // A global loads: row ar, k-offset ac (8 floats per thread per tile)
    const int ar = tid >> 1;
    const int ac = (tid & 1) * 8;
    const int ac2 = ac >> 1; // word k2 base: 0 or 4
    const float* Ag = A + (long long)(m0 + ar) * lda + ac;
    // B global loads
    const float* Bg;
    int kp = 0, nn = 0;
    if (B_TRANS) {
        Bg = Bm + (long long)(n0 + ar) * ldb + ac;
    } else {
        kp = tid >> 5;            // 0..7 (k2 within tile)
        nn = (tid & 31) * 4;      // 0..124
        Bg = Bm + (long long)(2 * kp) * ldb + n0 + nn;
    }

    float acc[4][4][4];
#pragma unroll
    for (int i = 0; i < 4; i++)
#pragma unroll
        for (int j = 0; j < 4; j++)
#pragma unroll
            for (int c = 0; c < 4; c++) acc[i][j][c] = 0.0f;

    const int nk = K >> 4;
    float4 a0v, a1v, b0v, b1v;
    a0v = *(const float4*)Ag;
    a1v = *(const float4*)(Ag + 4);
    if (B_TRANS) {
        b0v = *(const float4*)Bg;
        b1v = *(const float4*)(Bg + 4);
    } else {
        b0v = *(const float4*)Bg;            // row 2kp
        b1v = *(const float4*)(Bg + ldb);    // row 2kp+1
    }

#define STORE_TILES(BUF)                                                      \
    {                                                                         \
        float va[8] = {a0v.x, a0v.y, a0v.z, a0v.w, a1v.x, a1v.y, a1v.z, a1v.w}; \
        _Pragma("unroll")                                                     \
        for (int j = 0; j < 4; j++) {                                         \
            unsigned h, l;                                                    \
            bf16_split2(va[2 * j], va[2 * j + 1], h, l);                      \
            Ahi[(BUF) * 1088 + (ac2 + j) * 136 + ar] = h;                     \
            Alo[(BUF) * 1088 + (ac2 + j) * 136 + ar] = l;                     \
        }                                                                     \
        if (B_TRANS) {                                                        \
            float vb[8] = {b0v.x, b0v.y, b0v.z, b0v.w, b1v.x, b1v.y, b1v.z, b1v.w}; \
            _Pragma("unroll")                                                 \
            for (int j = 0; j < 4; j++) {                                     \
                unsigned h, l;                                                \
                bf16_split2(vb[2 * j], vb[2 * j + 1], h, l);                  \
                Bhi[(BUF) * 1088 + (ac2 + j) * 136 + ar] = h;                 \
                Blo[(BUF) * 1088 + (ac2 + j) * 136 + ar] = l;                 \
            }                                                                 \
        } else {                                                              \
            float r0[4] = {b0v.x, b0v.y, b0v.z, b0v.w};                       \
            float r1[4] = {b1v.x, b1v.y, b1v.z, b1v.w};                       \
            _Pragma("unroll")                                                 \
            for (int j = 0; j < 4; j++) {                                     \
                unsigned h, l;                                                \
                bf16_split2(r0[j], r1[j], h, l); /* low half = even k */      \
                Bhi[(BUF) * 1088 + kp * 136 + nn + j] = h;                    \
                Blo[(BUF) * 1088 + kp * 136 + nn + j] = l;                    \
            }                                                                 \
        }                                                                     \
    }

    STORE_TILES(0);
    __syncthreads();

    int p = 0;
    for (int kt = 0; kt < nk; ++kt) {
        if (kt + 1 < nk) {
            const float* Agn = Ag + (long long)(kt + 1) * 16;
            a0v = *(const float4*)Agn;
            a1v = *(const float4*)(Agn + 4);
            if (B_TRANS) {
                const float* Bgn = Bg + (long long)(kt + 1) * 16;
                b0v = *(const float4*)Bgn;
                b1v = *(const float4*)(Bgn + 4);
            } else {
                const float* Bgn = Bg + (long long)(kt + 1) * 16 * ldb;
                b0v = *(const float4*)Bgn;
                b1v = *(const float4*)(Bgn + ldb);
            }
        }

        const int base = p * 1088;
        // B fragments
        unsigned bh[4][2], bl[4][2];
#pragma unroll
        for (int nt = 0; nt < 4; nt++) {
            int nc = warp_n * 32 + nt * 8 + gr;
            bh[nt][0] = Bhi[base + tg * 136 + nc];
            bh[nt][1] = Bhi[base + (tg + 4) * 136 + nc];
            bl[nt][0] = Blo[base + tg * 136 + nc];
            bl[nt][1] = Blo[base + (tg + 4) * 136 + nc];
        }
#pragma unroll
        for (int mt = 0; mt < 4; mt++) {
            int mr = warp_m * 64 + mt * 16 + gr;
            unsigned ah0 = Ahi[base + tg * 136 + mr];
            unsigned ah1 = Ahi[base + tg * 136 + mr + 8];
            unsigned ah2 = Ahi[base + (tg + 4) * 136 + mr];
            unsigned ah3 = Ahi[base + (tg + 4) * 136 + mr + 8];
            unsigned al0 = Alo[base + tg * 136 + mr];
            unsigned al1 = Alo[base + tg * 136 + mr + 8];
            unsigned al2 = Alo[base + (tg + 4) * 136 + mr];
            unsigned al3 = Alo[base + (tg + 4) * 136 + mr + 8];
#pragma unroll
            for (int nt = 0; nt < 4; nt++) {
                MMA_BF16(acc[mt][nt], ah0, ah1, ah2, ah3, bh[nt][0], bh[nt][1]);
                MMA_BF16(acc[mt][nt], ah0, ah1, ah2, ah3, bl[nt][0], bl[nt][1]);
                MMA_BF16(acc[mt][nt], al0, al1, al2, al3, bh[nt][0], bh[nt][1]);
            }
        }

        if (kt + 1 < nk) STORE_TILES(p ^ 1);
        __syncthreads();
        p ^= 1;
    }
#undef STORE_TILES

    // epilogue: c0,c1 = row gr cols 2tg,2tg+1 ; c2,c3 = row gr+8
#pragma unroll
    for (int mt = 0; mt < 4; mt++) {
        int gm0 = m0 + warp_m * 64 + mt * 16 + gr;
#pragma unroll
        for (int nt = 0; nt < 4; nt++) {
            int gn = n0 + warp_n * 32 + nt * 8 + tg * 2;
            float2 v0 = make_float2(acc[mt][nt][0], acc[mt][nt][1]);
            float2 v1 = make_float2(acc[mt][nt][2], acc[mt][nt][3]);
            if (bias) {
                float2 bb = *(const float2*)&bias[gn];
                v0.x += bb.x; v0.y += bb.y;
                v1.x += bb.x; v1.y += bb.y;
            }
            float* c0p = C + (long long)gm0 * ldc + gn;
            float* c1p = c0p + 8 * (long long)ldc;
            if (accumulate) {
                float2 o0 = *(const float2*)c0p;
                float2 o1 = *(const float2*)c1p;
                v0.x += o0.x; v0.y += o0.y;
                v1.x += o1.x; v1.y += o1.y;
            }
            *(float2*)c0p = v0;
            *(float2*)c1p = v1;
        }
    }
}

// ======================================================================
// Per-step LSTM gate GEMM: C[64,4096] = h_prev[64,1024] * W_hh[4096,1024]^T
// (proven R6/R7 version)
// ======================================================================
__global__ __launch_bounds__(256) void gemm64(
    const float* __restrict__ A, int lda,
    const float* __restrict__ Bm,
    float* __restrict__ C)
{
    __shared__ float As[2][16][68];
    __shared__ float Bs[2][16][36];

    const int n0 = blockIdx.x * 32;
    const int tid = threadIdx.x;
    const int tx = tid & 15, ty = tid >> 4;

    const int ar = tid >> 2;
    const int ac = (tid & 3) * 4;
    const float* Ag = A + (long long)ar * lda + ac;
    const int br = tid >> 2;
    const float* Bg = Bm + (long long)(n0 + (br & 31)) * DH + ac;
    const bool bload = (tid < 128);

    float acc[4][2];
#pragma unroll
    for (int i = 0; i < 4; i++) { acc[i][0] = 0.0f; acc[i][1] = 0.0f; }

    const int nk = DH / 16;
    float4 av = *(const float4*)Ag;
    float4 bv = bload ? *(const float4*)Bg : make_float4(0, 0, 0, 0);

    As[0][ac + 0][ar] = av.x; As[0][ac + 1][ar] = av.y;
    As[0][ac + 2][ar] = av.z; As[0][ac + 3][ar] = av.w;
    if (bload) {
        Bs[0][ac + 0][br] = bv.x; Bs[0][ac + 1][br] = bv.y;
        Bs[0][ac + 2][br] = bv.z; Bs[0][ac + 3][br] = bv.w;
    }
    __syncthreads();

    int p = 0;
    for (int kt = 0; kt < nk; ++kt) {
        if (kt + 1 < nk) {
            av = *(const float4*)(Ag + (kt + 1) * 16);
            if (bload) bv = *(const float4*)(Bg + (kt + 1) * 16);
        }
#pragma unroll
        for (int k = 0; k < 16; ++k) {
            float4 a = *(const float4*)&As[p][k][ty * 4];
            float2 b = *(const float2*)&Bs[p][k][tx * 2];
            acc[0][0] += a.x * b.x; acc[0][1] += a.x * b.y;
            acc[1][0] += a.y * b.x; acc[1][1] += a.y * b.y;
            acc[2][0] += a.z * b.x; acc[2][1] += a.z * b.y;
            acc[3][0] += a.w * b.x; acc[3][1] += a.w * b.y;
        }
        if (kt + 1 < nk) {
            int q = p ^ 1;
            As[q][ac + 0][ar] = av.x; As[q][ac + 1][ar] = av.y;
            As[q][ac + 2][ar] = av.z; As[q][ac + 3][ar] = av.w;
            if (bload) {
                Bs[q][ac + 0][br] = bv.x; Bs[q][ac + 1][br] = bv.y;
                Bs[q][ac + 2][br] = bv.z; Bs[q][ac + 3][br] = bv.w;
            }
        }
        __syncthreads();
        p ^= 1;
    }

#pragma unroll
    for (int i = 0; i < 4; i++) {
        int gm = ty * 4 + i;
        float2 v = make_float2(acc[i][0], acc[i][1]);
        *(float2*)&C[(long long)gm * (4 * DH) + n0 + tx * 2] = v;
    }
}

// ======================================================================
// Small generic GEMM (bridge only): C = tanh(A*B^T + bias)
// ======================================================================
template <int TM, int TN>
__global__ __launch_bounds__(256) void gemm_small(
    int M, int N, int K,
    const float* __restrict__ A, int lda,
    const float* __restrict__ Bm, int ldb,
    float* __restrict__ C, int ldc,
    const float* __restrict__ bias)
{
    constexpr int BM = 16 * TM, BN = 16 * TN, BK = 16;
    __shared__ float As[BK][BM + 4];
    __shared__ float Bs[BK][BN + 4];
    int m0 = blockIdx.y * BM, n0 = blockIdx.x * BN;
    int tid = threadIdx.x;
    int rm = (tid / 16) * TM, rn = (tid % 16) * TN;
    float acc[TM][TN];
#pragma unroll
    for (int i = 0; i < TM; i++)
#pragma unroll
        for (int j = 0; j < TN; j++) acc[i][j] = 0.0f;
    for (int k0 = 0; k0 < K; k0 += BK) {
        for (int i = tid; i < BM * BK; i += 256) {
            int kk = i % BK, m = i / BK;
            int gm = m0 + m, gk = k0 + kk;
            As[kk][m] = (gm < M) ? A[(long long)gm * lda + gk] : 0.0f;
        }
        for (int i = tid; i < BN * BK; i += 256) {
            int kk = i % BK, n = i / BK;
            int gn = n0 + n, gk = k0 + kk;
            Bs[kk][n] = (gn < N) ? Bm[(long long)gn * ldb + gk] : 0.0f;
        }
        __syncthreads();
#pragma unroll
        for (int kk = 0; kk < BK; kk++) {
            float a[TM], bb[TN];
#pragma unroll
            for (int i = 0; i < TM; i++) a[i] = As[kk][rm + i];
#pragma unroll
            for (int j = 0; j < TN; j++) bb[j] = Bs[kk][rn + j];
#pragma unroll
            for (int i = 0; i < TM; i++)
#pragma unroll
                for (int j = 0; j < TN; j++) acc[i][j] += a[i] * bb[j];
        }
        __syncthreads();
    }
#pragma unroll
    for (int i = 0; i < TM; i++) {
        int gm = m0 + rm + i;
        if (gm >= M) continue;
#pragma unroll
        for (int j = 0; j < TN; j++) {
            int gn = n0 + rn + j;
            if (gn >= N) continue;
            C[(long long)gm * ldc + gn] = tanh_f(acc[i][j] + bias[gn]);
        }
    }
}

// ======================================================================
__global__ __launch_bounds__(256) void lstm_cell(
    const float* __restrict__ gates_hh, const float* __restrict__ xg_t,
    float* __restrict__ c, float* __restrict__ hout)
{
    int idx = blockIdx.x * 256 + threadIdx.x;
    int b = idx >> 10, h = idx & 1023;
    const float* gh = gates_hh + b * 4096;
    const float* xg = xg_t + (long long)b * (DT * 4096);
    float ig = gh[h] + xg[h];
    float fg = gh[1024 + h] + xg[1024 + h];
    float gg = gh[2048 + h] + xg[2048 + h];
    float og = gh[3072 + h] + xg[3072 + h];
    float cv = sigmoid_f(fg) * c[idx] + sigmoid_f(ig) * tanh_f(gg);
    c[idx] = cv;
    hout[(long long)b * (DT * DH) + h] = sigmoid_f(og) * tanh_f(cv);
}

// energy[b,t,s] = sum_h tanh(q[b,t,h] + pk[b,s,h]) * v[h]  (mask all-true)
__global__ __launch_bounds__(256) void energy_kernel(
    const float* __restrict__ q, const float* __restrict__ pk,
    const float* __restrict__ v, float* __restrict__ out)
{
    int b = blockIdx.z;
    int t0 = blockIdx.y * 32, s0 = blockIdx.x * 32;
    __shared__ float Qs[32][33], Ps[32][33], Vs[32];
    int tid = threadIdx.x;
    int hh = tid & 31, r = tid >> 5;
    int tr = (tid / 16) * 2, sc = (tid % 16) * 2;
    const float* qb = q + ((long long)b * DT + t0) * DH;
    const float* pb = pk + ((long long)b * DS + s0) * DH;
    float a00 = 0, a01 = 0, a10 = 0, a11 = 0;

    for (int h0 = 0; h0 < DH; h0 += 32) {
#pragma unroll
        for (int rr = 0; rr < 4; rr++) {
            int row = r + rr * 8;
            Qs[hh][row] = qb[(long long)row * DH + h0 + hh];
            Ps[hh][row] = pb[(long long)row * DH + h0 + hh];
        }
        if (tid < 32) Vs[tid] = v[h0 + tid];
        __syncthreads();
#pragma unroll 8
        for (int k = 0; k < 32; k++) {
            float vv = Vs[k];
            float q0 = Qs[k][tr], q1 = Qs[k][tr + 1];
            float p0 = Ps[k][sc], p1 = Ps[k][sc + 1];
            a00 += tanh_a(q0 + p0) * vv;
            a01 += tanh_a(q0 + p1) * vv;
            a10 += tanh_a(q1 + p0) * vv;
            a11 += tanh_a(q1 + p1) * vv;
        }
        __syncthreads();
    }
    float* o0 = out + ((long long)b * DT + t0 + tr) * DS + s0 + sc;
    float* o1 = o0 + DS;
    o0[0] = a00; o0[1] = a01;
    o1[0] = a10; o1[1] = a11;
}

__global__ __launch_bounds__(256) void softmax_kernel(float* __restrict__ p)
{
    int row = blockIdx.x * 8 + (threadIdx.x >> 5);
    int lane = threadIdx.x & 31;
    float* pr = p + (long long)row * DS;
    float vals[8];
    float mx = -3.0e38f;
#pragma unroll
    for (int j = 0; j < 8; j++) { vals[j] = pr[lane + j * 32]; mx = fmaxf(mx, vals[j]); }
#pragma unroll
    for (int o = 16; o > 0; o >>= 1) mx = fmaxf(mx, __shfl_xor_sync(0xFFFFFFFFu, mx, o));
    float sum = 0.0f;
#pragma unroll
    for (int j = 0; j < 8; j++) { vals[j] = __expf(vals[j] - mx); sum += vals[j]; }
#pragma unroll
    for (int o = 16; o > 0; o >>= 1) sum += __shfl_xor_sync(0xFFFFFFFFu, sum, o);
    float inv = __fdividef(1.0f, sum);
#pragma unroll
    for (int j = 0; j < 8; j++) pr[lane + j * 32] = vals[j] * inv;
}

__global__ __launch_bounds__(256) void copy_hfinal(
    const float* __restrict__ hseq, float* __restrict__ out)
{
    int idx = blockIdx.x * 256 + threadIdx.x;
    int b = idx >> 10, h = idx & 1023;
    out[idx] = hseq[((long long)b * DT + (DT - 1)) * DH + h];
}

// ======================================================================
extern "C" void kernel_launch(void* const* d_in, const int* in_sizes, int n_in,
                              void* d_out, int out_size)
{
    const float* trg      = (const float*)d_in[0];
    const float* enc      = (const float*)d_in[1];
    const float* ehf      = (const float*)d_in[2];
    const float* ecf      = (const float*)d_in[3];
    const float* W_ih     = (const float*)d_in[6];
    const float* W_hh     = (const float*)d_in[7];
    const float* b_lstm   = (const float*)d_in[8];
    const float* W_bridge = (const float*)d_in[9];
    const float* b_bridge = (const float*)d_in[10];
    const float* W_key    = (const float*)d_in[11];
    const float* W_query  = (const float*)d_in[12];
    const float* v_energy = (const float*)d_in[13];
    const float* W_pre    = (const float*)d_in[14];

    float* out  = (float*)d_out;
    float* hseq = out;
    float* hfin = out + (long long)DB * DT * DH;
    float* pre  = hfin + (long long)DB * DH;

    float *p_xg, *p_pk, *p_q, *p_probs, *p_ctx, *p_h0, *p_c, *p_gates;
    cudaGetSymbolAddress((void**)&p_xg, g_xgates);
    cudaGetSymbolAddress((void**)&p_pk, g_projkey);
    cudaGetSymbolAddress((void**)&p_q, g_q);
    cudaGetSymbolAddress((void**)&p_probs, g_probs);
    cudaGetSymbolAddress((void**)&p_ctx, g_ctx);
    cudaGetSymbolAddress((void**)&p_h0, g_h0);
    cudaGetSymbolAddress((void**)&p_c, g_c);
    cudaGetSymbolAddress((void**)&p_gates, g_gates);

    const int BT = DB * DT; // 16384

    // Bridge
    gemm_small<4, 2><<<dim3(DH / 32, 1, 1), 256>>>(
        DB, DH, 2 * DH, ehf, 2 * DH, W_bridge, 2 * DH, p_h0, DH, b_bridge);
    gemm_small<4, 2><<<dim3(DH / 32, 1, 1), 256>>>(
        DB, DH, 2 * DH, ecf, 2 * DH, W_bridge, 2 * DH, p_c, DH, b_bridge);

    // x_gates = trg @ W_ih^T + b_lstm : [16384, 4096] K=256
    gemm_bf16<true><<<dim3(32, 128, 1), 256>>>(
        BT, 4 * DH, DE, trg, DE, 0, W_ih, DE, 0,
        p_xg, 4 * DH, 0, b_lstm, 0);

    // proj_key = enc @ W_key^T : [16384, 1024] K=2048
    gemm_bf16<true><<<dim3(8, 128, 1), 256>>>(
        BT, DH, 2 * DH, enc, 2 * DH, 0, W_key, 2 * DH, 0,
        p_pk, DH, 0, nullptr, 0);

    // Sequential LSTM (proven FFMA path)
    for (int t = 0; t < DT; t++) {
        const float* hprev = (t == 0) ? p_h0 : (hseq + (long long)(t - 1) * DH);
        int lda = (t == 0) ? DH : (DT * DH);
        gemm64<<<128, 256>>>(hprev, lda, W_hh, p_gates);
        lstm_cell<<<DB * DH / 256, 256>>>(
            p_gates, p_xg + (long long)t * 4 * DH, p_c, hseq + (long long)t * DH);
    }

    // q = h_seq @ W_query^T : [16384, 1024] K=1024
    gemm_bf16<true><<<dim3(8, 128, 1), 256>>>(
        BT, DH, DH, hseq, DH, 0, W_query, DH, 0,
        p_q, DH, 0, nullptr, 0);

    // energy + softmax
    energy_kernel<<<dim3(DS / 32, DT / 32, DB), 256>>>(p_q, p_pk, v_energy, p_probs);
    softmax_kernel<<<BT / 8, 256>>>(p_probs);

    // ctx[b] = probs[b] @ enc[b] : batched NN [256,256]x[256,2048]
    gemm_bf16<false><<<dim3(16, 2, DB), 256>>>(
        DT, 2 * DH, DS,
        p_probs, DS, (long long)DT * DS,
        enc, 2 * DH, (long long)DS * 2 * DH,
        p_ctx, 2 * DH, (long long)DT * 2 * DH, nullptr, 0);

    // pre = [trg | h_seq | ctx] @ W_pre^T : three accumulating GEMMs
    gemm_bf16<true><<<dim3(8, 128, 1), 256>>>(
        BT, DH, DE, trg, DE, 0, W_pre, 3328, 0,
        pre, DH, 0, nullptr, 0);
    gemm_bf16<true><<<dim3(8, 128, 1), 256>>>(
        BT, DH, DH, hseq, DH, 0, W_pre + DE, 3328, 0,
        pre, DH, 0, nullptr, 1);
    gemm_bf16<true><<<dim3(8, 128, 1), 256>>>(
        BT, DH, 2 * DH, p_ctx, 2 * DH, 0, W_pre + DE + DH, 3328, 0,
        pre, DH, 0, nullptr, 1);

    copy_hfinal<<<DB * DH / 256, 256>>>(hseq, hfin);
}

// round 11
// speedup vs baseline: 1.6572x; 1.3413x over previous
#include <cuda_runtime.h>
#include <cuda_bf16.h>
#include <math.h>

// Dims (fixed): B=64, T=256, S=256, E=256, H=1024
#define DB 64
#define DT 256
#define DS 256
#define DE 256
#define DH 1024

// ---- static scratch ----
__device__ float g_xgates[(size_t)DB * DT * 4 * DH]; // [B*T, 4H]
__device__ float g_projkey[(size_t)DB * DS * DH];    // [B*S, H]
__device__ float g_q[(size_t)DB * DT * DH];          // [B*T, H]
__device__ float g_probs[(size_t)DB * DT * DS];      // [B*T, S]
__device__ float g_ctx[(size_t)DB * DT * 2 * DH];    // [B*T, 2H]
__device__ float g_h0[DB * DH];
__device__ float g_c[DB * DH];
__device__ float g_gates[DB * 4 * DH];
__device__ __nv_bfloat16 g_whi[(size_t)4 * DH * DH]; // W_hh split hi
__device__ __nv_bfloat16 g_wlo[(size_t)4 * DH * DH]; // W_hh split lo

__device__ __forceinline__ float tanh_f(float x) {
    float e = __expf(2.0f * x);
    return 1.0f - __fdividef(2.0f, e + 1.0f);
}
__device__ __forceinline__ float tanh_a(float x) {
    float y;
    asm("tanh.approx.f32 %0, %1;" : "=f"(y) : "f"(x));
    return y;
}
__device__ __forceinline__ float sigmoid_f(float x) {
    return __fdividef(1.0f, 1.0f + __expf(-x));
}

// split two floats into packed bf16x2 hi + lo words (elem0 in low half)
__device__ __forceinline__ void bf16_split2(float x0, float x1,
                                            unsigned& hi, unsigned& lo) {
    __nv_bfloat16 h0 = __float2bfloat16(x0), h1 = __float2bfloat16(x1);
    float r0 = x0 - __bfloat162float(h0);
    float r1 = x1 - __bfloat162float(h1);
    __nv_bfloat16 l0 = __float2bfloat16(r0), l1 = __float2bfloat16(r1);
    hi = ((unsigned)__bfloat16_as_ushort(h1) << 16) | __bfloat16_as_ushort(h0);
    lo = ((unsigned)__bfloat16_as_ushort(l1) << 16) | __bfloat16_as_ushort(l0);
}

#define MMA_BF16(d, a0, a1, a2, a3, b0, b1)                                   \
    asm volatile(                                                             \
        "mma.sync.aligned.m16n8k16.row.col.f32.bf16.bf16.f32 "                \
        "{%0,%1,%2,%3}, {%4,%5,%6,%7}, {%8,%9}, {%0,%1,%2,%3};"               \
        : "+f"(d[0]), "+f"(d[1]), "+f"(d[2]), "+f"(d[3])                      \
        : "r"(a0), "r"(a1), "r"(a2), "r"(a3), "r"(b0), "r"(b1))

// one-time W_hh f32 -> bf16 hi/lo split
__global__ __launch_bounds__(256) void split_w(
    const float* __restrict__ W,
    __nv_bfloat16* __restrict__ whi, __nv_bfloat16* __restrict__ wlo)
{
    int i = blockIdx.x * 256 + threadIdx.x;
    float w = W[i];
    __nv_bfloat16 h = __float2bfloat16(w);
    whi[i] = h;
    wlo[i] = __float2bfloat16(w - __bfloat162float(h));
}

// ======================================================================
// bf16x3-split tensor-core GEMM (near-fp32 accuracy).
// Block tile 128x128, BK=16, 256 threads (8 warps 2x4), warp tile 64x32.
// ======================================================================
template <bool B_TRANS>
__global__ __launch_bounds__(256, 2) void gemm_bf16(
    int M, int N, int K,
    const float* __restrict__ A, int lda, long long sA,
    const float* __restrict__ Bm, int ldb, long long sB,
    float* __restrict__ C, int ldc, long long sC,
    const float* __restrict__ bias, int accumulate)
{
    __shared__ unsigned Ahi[2 * 8 * 136], Alo[2 * 8 * 136];
    __shared__ unsigned Bhi[2 * 8 * 136], Blo[2 * 8 * 136];

    const int bz = blockIdx.z;
    A += (long long)bz * sA;
    Bm += (long long)bz * sB;
    C += (long long)bz * sC;

    const int m0 = blockIdx.y * 128, n0 = blockIdx.x * 128;
    const int tid = threadIdx.x;
    const int wid = tid >> 5, lane = tid & 31;
    const int warp_m = wid >> 2, warp_n = wid & 3;
    const int tg = lane & 3, gr = lane >> 2;

    const int ar = tid >> 1;
    const int ac = (tid & 1) * 8;
    const int ac2 = ac >> 1;
    const float* Ag = A + (long long)(m0 + ar) * lda + ac;
    const float* Bg;
    int kp = 0, nn = 0;
    if (B_TRANS) {
        Bg = Bm + (long long)(n0 + ar) * ldb + ac;
    } else {
        kp = tid >> 5;
        nn = (tid & 31) * 4;
        Bg = Bm + (long long)(2 * kp) * ldb + n0 + nn;
    }

    float acc[4][4][4];
#pragma unroll
    for (int i = 0; i < 4; i++)
#pragma unroll
        for (int j = 0; j < 4; j++)
#pragma unroll
            for (int c = 0; c < 4; c++) acc[i][j][c] = 0.0f;

    const int nk = K >> 4;
    float4 a0v, a1v, b0v, b1v;
    a0v = *(const float4*)Ag;
    a1v = *(const float4*)(Ag + 4);
    if (B_TRANS) {
        b0v = *(const float4*)Bg;
        b1v = *(const float4*)(Bg + 4);
    } else {
        b0v = *(const float4*)Bg;
        b1v = *(const float4*)(Bg + ldb);
    }

#define STORE_TILES(BUF)                                                      \
    {                                                                         \
        float va[8] = {a0v.x, a0v.y, a0v.z, a0v.w, a1v.x, a1v.y, a1v.z, a1v.w}; \
        _Pragma("unroll")                                                     \
        for (int j = 0; j < 4; j++) {                                         \
            unsigned h, l;                                                    \
            bf16_split2(va[2 * j], va[2 * j + 1], h, l);                      \
            Ahi[(BUF) * 1088 + (ac2 + j) * 136 + ar] = h;                     \
            Alo[(BUF) * 1088 + (ac2 + j) * 136 + ar] = l;                     \
        }                                                                     \
        if (B_TRANS) {                                                        \
            float vb[8] = {b0v.x, b0v.y, b0v.z, b0v.w, b1v.x, b1v.y, b1v.z, b1v.w}; \
            _Pragma("unroll")                                                 \
            for (int j = 0; j < 4; j++) {                                     \
                unsigned h, l;                                                \
                bf16_split2(vb[2 * j], vb[2 * j + 1], h, l);                  \
                Bhi[(BUF) * 1088 + (ac2 + j) * 136 + ar] = h;                 \
                Blo[(BUF) * 1088 + (ac2 + j) * 136 + ar] = l;                 \
            }                                                                 \
        } else {                                                              \
            float r0[4] = {b0v.x, b0v.y, b0v.z, b0v.w};                       \
            float r1[4] = {b1v.x, b1v.y, b1v.z, b1v.w};                       \
            _Pragma("unroll")                                                 \
            for (int j = 0; j < 4; j++) {                                     \
                unsigned h, l;                                                \
                bf16_split2(r0[j], r1[j], h, l);                              \
                Bhi[(BUF) * 1088 + kp * 136 + nn + j] = h;                    \
                Blo[(BUF) * 1088 + kp * 136 + nn + j] = l;                    \
            }                                                                 \
        }                                                                     \
    }

    STORE_TILES(0);
    __syncthreads();

    int p = 0;
    for (int kt = 0; kt < nk; ++kt) {
        if (kt + 1 < nk) {
            const float* Agn = Ag + (long long)(kt + 1) * 16;
            a0v = *(const float4*)Agn;
            a1v = *(const float4*)(Agn + 4);
            if (B_TRANS) {
                const float* Bgn = Bg + (long long)(kt + 1) * 16;
                b0v = *(const float4*)Bgn;
                b1v = *(const float4*)(Bgn + 4);
            } else {
                const float* Bgn = Bg + (long long)(kt + 1) * 16 * ldb;
                b0v = *(const float4*)Bgn;
                b1v = *(const float4*)(Bgn + ldb);
            }
        }

        const int base = p * 1088;
        unsigned bh[4][2], bl[4][2];
#pragma unroll
        for (int nt = 0; nt < 4; nt++) {
            int nc = warp_n * 32 + nt * 8 + gr;
            bh[nt][0] = Bhi[base + tg * 136 + nc];
            bh[nt][1] = Bhi[base + (tg + 4) * 136 + nc];
            bl[nt][0] = Blo[base + tg * 136 + nc];
            bl[nt][1] = Blo[base + (tg + 4) * 136 + nc];
        }
#pragma unroll
        for (int mt = 0; mt < 4; mt++) {
            int mr = warp_m * 64 + mt * 16 + gr;
            unsigned ah0 = Ahi[base + tg * 136 + mr];
            unsigned ah1 = Ahi[base + tg * 136 + mr + 8];
            unsigned ah2 = Ahi[base + (tg + 4) * 136 + mr];
            unsigned ah3 = Ahi[base + (tg + 4) * 136 + mr + 8];
            unsigned al0 = Alo[base + tg * 136 + mr];
            unsigned al1 = Alo[base + tg * 136 + mr + 8];
            unsigned al2 = Alo[base + (tg + 4) * 136 + mr];
            unsigned al3 = Alo[base + (tg + 4) * 136 + mr + 8];
#pragma unroll
            for (int nt = 0; nt < 4; nt++) {
                MMA_BF16(acc[mt][nt], ah0, ah1, ah2, ah3, bh[nt][0], bh[nt][1]);
                MMA_BF16(acc[mt][nt], ah0, ah1, ah2, ah3, bl[nt][0], bl[nt][1]);
                MMA_BF16(acc[mt][nt], al0, al1, al2, al3, bh[nt][0], bh[nt][1]);
            }
        }

        if (kt + 1 < nk) STORE_TILES(p ^ 1);
        __syncthreads();
        p ^= 1;
    }
#undef STORE_TILES

#pragma unroll
    for (int mt = 0; mt < 4; mt++) {
        int gm0 = m0 + warp_m * 64 + mt * 16 + gr;
#pragma unroll
        for (int nt = 0; nt < 4; nt++) {
            int gn = n0 + warp_n * 32 + nt * 8 + tg * 2;
            float2 v0 = make_float2(acc[mt][nt][0], acc[mt][nt][1]);
            float2 v1 = make_float2(acc[mt][nt][2], acc[mt][nt][3]);
            if (bias) {
                float2 bb = *(const float2*)&bias[gn];
                v0.x += bb.x; v0.y += bb.y;
                v1.x += bb.x; v1.y += bb.y;
            }
            float* c0p = C + (long long)gm0 * ldc + gn;
            float* c1p = c0p + 8 * (long long)ldc;
            if (accumulate) {
                float2 o0 = *(const float2*)c0p;
                float2 o1 = *(const float2*)c1p;
                v0.x += o0.x; v0.y += o0.y;
                v1.x += o1.x; v1.y += o1.y;
            }
            *(float2*)c0p = v0;
            *(float2*)c1p = v1;
        }
    }
}

// ======================================================================
// Per-step LSTM gate GEMM (tensor cores, pre-split W):
// C[64,4096] = h_prev[64,1024] * W_hh^T via bf16x3.
// grid 128 (N-tile 32), 256 threads, 8 warps = 4(m) x 2(n), warp tile 16x16.
// BK=32. A split inline from f32; B read as pre-split bf16 (L2-resident).
// ======================================================================
__global__ __launch_bounds__(256, 2) void gemm_step(
    const float* __restrict__ hprev, int lda,
    const __nv_bfloat16* __restrict__ whi_, const __nv_bfloat16* __restrict__ wlo_,
    float* __restrict__ C)
{
    const unsigned* Whi = (const unsigned*)whi_;
    const unsigned* Wlo = (const unsigned*)wlo_;
    __shared__ unsigned Ahi[2][16][68], Alo[2][16][68];
    __shared__ unsigned Bhi[2][16][36], Blo[2][16][36];

    const int n0 = blockIdx.x * 32;
    const int tid = threadIdx.x;
    const int wid = tid >> 5, lane = tid & 31;
    const int warp_m = wid >> 1, warp_n = wid & 1;
    const int tg = lane & 3, gr = lane >> 2;

    // A: row ar (batch), k-offset ak (8 floats)
    const int ar = tid >> 2;        // 0..63
    const int ak = (tid & 3) * 8;   // 0,8,16,24
    const float* Ag = hprev + (long long)ar * lda + ak;
    // B: col bn, word-pair bk2 (uint2 = words bk2,bk2+1)
    const int bn = tid >> 3;        // 0..31
    const int bk2 = (tid & 7) * 2;  // 0..14
    const unsigned* BgH = Whi + (((long long)(n0 + bn)) << 9) + bk2;
    const unsigned* BgL = Wlo + (((long long)(n0 + bn)) << 9) + bk2;

    float acc[2][4];
#pragma unroll
    for (int i = 0; i < 2; i++)
#pragma unroll
        for (int j = 0; j < 4; j++) acc[i][j] = 0.0f;

    const int NK = DH / 32; // 32
    float4 a0 = *(const float4*)Ag;
    float4 a1 = *(const float4*)(Ag + 4);
    uint2 bh = *(const uint2*)BgH;
    uint2 bl = *(const uint2*)BgL;

#define GS_STORE(BUF)                                                         \
    {                                                                         \
        float va[8] = {a0.x, a0.y, a0.z, a0.w, a1.x, a1.y, a1.z, a1.w};       \
        _Pragma("unroll")                                                     \
        for (int j = 0; j < 4; j++) {                                         \
            unsigned h, l;                                                    \
            bf16_split2(va[2 * j], va[2 * j + 1], h, l);                      \
            Ahi[BUF][(ak >> 1) + j][ar] = h;                                  \
            Alo[BUF][(ak >> 1) + j][ar] = l;                                  \
        }                                                                     \
        Bhi[BUF][bk2][bn] = bh.x;                                             \
        Bhi[BUF][bk2 + 1][bn] = bh.y;                                         \
        Blo[BUF][bk2][bn] = bl.x;                                             \
        Blo[BUF][bk2 + 1][bn] = bl.y;                                         \
    }

    GS_STORE(0);
    __syncthreads();

    int p = 0;
    for (int kt = 0; kt < NK; ++kt) {
        if (kt + 1 < NK) {
            const float* Agn = Ag + (kt + 1) * 32;
            a0 = *(const float4*)Agn;
            a1 = *(const float4*)(Agn + 4);
            bh = *(const uint2*)(BgH + (kt + 1) * 16);
            bl = *(const uint2*)(BgL + (kt + 1) * 16);
        }
#pragma unroll
        for (int s = 0; s < 2; ++s) {
            const int kb = s * 8;
            const int mr = warp_m * 16 + gr;
            unsigned ah0 = Ahi[p][kb + tg][mr];
            unsigned ah1 = Ahi[p][kb + tg][mr + 8];
            unsigned ah2 = Ahi[p][kb + tg + 4][mr];
            unsigned ah3 = Ahi[p][kb + tg + 4][mr + 8];
            unsigned al0 = Alo[p][kb + tg][mr];
            unsigned al1 = Alo[p][kb + tg][mr + 8];
            unsigned al2 = Alo[p][kb + tg + 4][mr];
            unsigned al3 = Alo[p][kb + tg + 4][mr + 8];
#pragma unroll
            for (int nt = 0; nt < 2; nt++) {
                int nc = warp_n * 16 + nt * 8 + gr;
                unsigned b0h = Bhi[p][kb + tg][nc];
                unsigned b1h = Bhi[p][kb + tg + 4][nc];
                unsigned b0l = Blo[p][kb + tg][nc];
                unsigned b1l = Blo[p][kb + tg + 4][nc];
                MMA_BF16(acc[nt], ah0, ah1, ah2, ah3, b0h, b1h);
                MMA_BF16(acc[nt], ah0, ah1, ah2, ah3, b0l, b1l);
                MMA_BF16(acc[nt], al0, al1, al2, al3, b0h, b1h);
            }
        }
        if (kt + 1 < NK) GS_STORE(p ^ 1);
        __syncthreads();
        p ^= 1;
    }
#undef GS_STORE

    // epilogue: rows gr / gr+8 of warp_m*16 tile
#pragma unroll
    for (int nt = 0; nt < 2; nt++) {
        int gn = n0 + warp_n * 16 + nt * 8 + tg * 2;
        int gm = warp_m * 16 + gr;
        *(float2*)&C[(long long)gm * (4 * DH) + gn] =
            make_float2(acc[nt][0], acc[nt][1]);
        *(float2*)&C[(long long)(gm + 8) * (4 * DH) + gn] =
            make_float2(acc[nt][2], acc[nt][3]);
    }
}

// ======================================================================
// Small generic GEMM (bridge only): C = tanh(A*B^T + bias)
// ======================================================================
template <int TM, int TN>
__global__ __launch_bounds__(256) void gemm_small(
    int M, int N, int K,
    const float* __restrict__ A, int lda,
    const float* __restrict__ Bm, int ldb,
    float* __restrict__ C, int ldc,
    const float* __restrict__ bias)
{
    constexpr int BM = 16 * TM, BN = 16 * TN, BK = 16;
    __shared__ float As[BK][BM + 4];
    __shared__ float Bs[BK][BN + 4];
    int m0 = blockIdx.y * BM, n0 = blockIdx.x * BN;
    int tid = threadIdx.x;
    int rm = (tid / 16) * TM, rn = (tid % 16) * TN;
    float acc[TM][TN];
#pragma unroll
    for (int i = 0; i < TM; i++)
#pragma unroll
        for (int j = 0; j < TN; j++) acc[i][j] = 0.0f;
    for (int k0 = 0; k0 < K; k0 += BK) {
        for (int i = tid; i < BM * BK; i += 256) {
            int kk = i % BK, m = i / BK;
            int gm = m0 + m, gk = k0 + kk;
            As[kk][m] = (gm < M) ? A[(long long)gm * lda + gk] : 0.0f;
        }
        for (int i = tid; i < BN * BK; i += 256) {
            int kk = i % BK, n = i / BK;
            int gn = n0 + n, gk = k0 + kk;
            Bs[kk][n] = (gn < N) ? Bm[(long long)gn * ldb + gk] : 0.0f;
        }
        __syncthreads();
#pragma unroll
        for (int kk = 0; kk < BK; kk++) {
            float a[TM], bb[TN];
#pragma unroll
            for (int i = 0; i < TM; i++) a[i] = As[kk][rm + i];
#pragma unroll
            for (int j = 0; j < TN; j++) bb[j] = Bs[kk][rn + j];
#pragma unroll
            for (int i = 0; i < TM; i++)
#pragma unroll
                for (int j = 0; j < TN; j++) acc[i][j] += a[i] * bb[j];
        }
        __syncthreads();
    }
#pragma unroll
    for (int i = 0; i < TM; i++) {
        int gm = m0 + rm + i;
        if (gm >= M) continue;
#pragma unroll
        for (int j = 0; j < TN; j++) {
            int gn = n0 + rn + j;
            if (gn >= N) continue;
            C[(long long)gm * ldc + gn] = tanh_f(acc[i][j] + bias[gn]);
        }
    }
}

// ======================================================================
__global__ __launch_bounds__(256) void lstm_cell(
    const float* __restrict__ gates_hh, const float* __restrict__ xg_t,
    float* __restrict__ c, float* __restrict__ hout)
{
    int idx = blockIdx.x * 256 + threadIdx.x;
    int b = idx >> 10, h = idx & 1023;
    const float* gh = gates_hh + b * 4096;
    const float* xg = xg_t + (long long)b * (DT * 4096);
    float ig = gh[h] + xg[h];
    float fg = gh[1024 + h] + xg[1024 + h];
    float gg = gh[2048 + h] + xg[2048 + h];
    float og = gh[3072 + h] + xg[3072 + h];
    float cv = sigmoid_f(fg) * c[idx] + sigmoid_f(ig) * tanh_f(gg);
    c[idx] = cv;
    hout[(long long)b * (DT * DH) + h] = sigmoid_f(og) * tanh_f(cv);
}

// energy[b,t,s] = sum_h tanh(q[b,t,h] + pk[b,s,h]) * v[h]  (mask all-true)
__global__ __launch_bounds__(256) void energy_kernel(
    const float* __restrict__ q, const float* __restrict__ pk,
    const float* __restrict__ v, float* __restrict__ out)
{
    int b = blockIdx.z;
    int t0 = blockIdx.y * 32, s0 = blockIdx.x * 32;
    __shared__ float Qs[32][33], Ps[32][33], Vs[32];
    int tid = threadIdx.x;
    int hh = tid & 31, r = tid >> 5;
    int tr = (tid / 16) * 2, sc = (tid % 16) * 2;
    const float* qb = q + ((long long)b * DT + t0) * DH;
    const float* pb = pk + ((long long)b * DS + s0) * DH;
    float a00 = 0, a01 = 0, a10 = 0, a11 = 0;

    for (int h0 = 0; h0 < DH; h0 += 32) {
#pragma unroll
        for (int rr = 0; rr < 4; rr++) {
            int row = r + rr * 8;
            Qs[hh][row] = qb[(long long)row * DH + h0 + hh];
            Ps[hh][row] = pb[(long long)row * DH + h0 + hh];
        }
        if (tid < 32) Vs[tid] = v[h0 + tid];
        __syncthreads();
#pragma unroll 8
        for (int k = 0; k < 32; k++) {
            float vv = Vs[k];
            float q0 = Qs[k][tr], q1 = Qs[k][tr + 1];
            float p0 = Ps[k][sc], p1 = Ps[k][sc + 1];
            a00 += tanh_a(q0 + p0) * vv;
            a01 += tanh_a(q0 + p1) * vv;
            a10 += tanh_a(q1 + p0) * vv;
            a11 += tanh_a(q1 + p1) * vv;
        }
        __syncthreads();
    }
    float* o0 = out + ((long long)b * DT + t0 + tr) * DS + s0 + sc;
    float* o1 = o0 + DS;
    o0[0] = a00; o0[1] = a01;
    o1[0] = a10; o1[1] = a11;
}

__global__ __launch_bounds__(256) void softmax_kernel(float* __restrict__ p)
{
    int row = blockIdx.x * 8 + (threadIdx.x >> 5);
    int lane = threadIdx.x & 31;
    float* pr = p + (long long)row * DS;
    float vals[8];
    float mx = -3.0e38f;
#pragma unroll
    for (int j = 0; j < 8; j++) { vals[j] = pr[lane + j * 32]; mx = fmaxf(mx, vals[j]); }
#pragma unroll
    for (int o = 16; o > 0; o >>= 1) mx = fmaxf(mx, __shfl_xor_sync(0xFFFFFFFFu, mx, o));
    float sum = 0.0f;
#pragma unroll
    for (int j = 0; j < 8; j++) { vals[j] = __expf(vals[j] - mx); sum += vals[j]; }
#pragma unroll
    for (int o = 16; o > 0; o >>= 1) sum += __shfl_xor_sync(0xFFFFFFFFu, sum, o);
    float inv = __fdividef(1.0f, sum);
#pragma unroll
    for (int j = 0; j < 8; j++) pr[lane + j * 32] = vals[j] * inv;
}

__global__ __launch_bounds__(256) void copy_hfinal(
    const float* __restrict__ hseq, float* __restrict__ out)
{
    int idx = blockIdx.x * 256 + threadIdx.x;
    int b = idx >> 10, h = idx & 1023;
    out[idx] = hseq[((long long)b * DT + (DT - 1)) * DH + h];
}

// ======================================================================
extern "C" void kernel_launch(void* const* d_in, const int* in_sizes, int n_in,
                              void* d_out, int out_size)
{
    const float* trg      = (const float*)d_in[0];
    const float* enc      = (const float*)d_in[1];
    const float* ehf      = (const float*)d_in[2];
    const float* ecf      = (const float*)d_in[3];
    const float* W_ih     = (const float*)d_in[6];
    const float* W_hh     = (const float*)d_in[7];
    const float* b_lstm   = (const float*)d_in[8];
    const float* W_bridge = (const float*)d_in[9];
    const float* b_bridge = (const float*)d_in[10];
    const float* W_key    = (const float*)d_in[11];
    const float* W_query  = (const float*)d_in[12];
    const float* v_energy = (const float*)d_in[13];
    const float* W_pre    = (const float*)d_in[14];

    float* out  = (float*)d_out;
    float* hseq = out;
    float* hfin = out + (long long)DB * DT * DH;
    float* pre  = hfin + (long long)DB * DH;

    float *p_xg, *p_pk, *p_q, *p_probs, *p_ctx, *p_h0, *p_c, *p_gates;
    __nv_bfloat16 *p_whi, *p_wlo;
    cudaGetSymbolAddress((void**)&p_xg, g_xgates);
    cudaGetSymbolAddress((void**)&p_pk, g_projkey);
    cudaGetSymbolAddress((void**)&p_q, g_q);
    cudaGetSymbolAddress((void**)&p_probs, g_probs);
    cudaGetSymbolAddress((void**)&p_ctx, g_ctx);
    cudaGetSymbolAddress((void**)&p_h0, g_h0);
    cudaGetSymbolAddress((void**)&p_c, g_c);
    cudaGetSymbolAddress((void**)&p_gates, g_gates);
    cudaGetSymbolAddress((void**)&p_whi, g_whi);
    cudaGetSymbolAddress((void**)&p_wlo, g_wlo);

    const int BT = DB * DT; // 16384

    // One-time W_hh split (4M elems)
    split_w<<<(4 * DH * DH) / 256, 256>>>(W_hh, p_whi, p_wlo);

    // Bridge
    gemm_small<4, 2><<<dim3(DH / 32, 1, 1), 256>>>(
        DB, DH, 2 * DH, ehf, 2 * DH, W_bridge, 2 * DH, p_h0, DH, b_bridge);
    gemm_small<4, 2><<<dim3(DH / 32, 1, 1), 256>>>(
        DB, DH, 2 * DH, ecf, 2 * DH, W_bridge, 2 * DH, p_c, DH, b_bridge);

    // x_gates = trg @ W_ih^T + b_lstm : [16384, 4096] K=256
    gemm_bf16<true><<<dim3(32, 128, 1), 256>>>(
        BT, 4 * DH, DE, trg, DE, 0, W_ih, DE, 0,
        p_xg, 4 * DH, 0, b_lstm, 0);

    // proj_key = enc @ W_key^T : [16384, 1024] K=2048
    gemm_bf16<true><<<dim3(8, 128, 1), 256>>>(
        BT, DH, 2 * DH, enc, 2 * DH, 0, W_key, 2 * DH, 0,
        p_pk, DH, 0, nullptr, 0);

    // Sequential LSTM: tensor-core gate GEMM (pre-split W) + cell
    for (int t = 0; t < DT; t++) {
        const float* hprev = (t == 0) ? p_h0 : (hseq + (long long)(t - 1) * DH);
        int lda = (t == 0) ? DH : (DT * DH);
        gemm_step<<<128, 256>>>(hprev, lda, p_whi, p_wlo, p_gates);
        lstm_cell<<<DB * DH / 256, 256>>>(
            p_gates, p_xg + (long long)t * 4 * DH, p_c, hseq + (long long)t * DH);
    }

    // q = h_seq @ W_query^T : [16384, 1024] K=1024
    gemm_bf16<true><<<dim3(8, 128, 1), 256>>>(
        BT, DH, DH, hseq, DH, 0, W_query, DH, 0,
        p_q, DH, 0, nullptr, 0);

    // energy + softmax
    energy_kernel<<<dim3(DS / 32, DT / 32, DB), 256>>>(p_q, p_pk, v_energy, p_probs);
    softmax_kernel<<<BT / 8, 256>>>(p_probs);

    // ctx[b] = probs[b] @ enc[b] : batched NN [256,256]x[256,2048]
    gemm_bf16<false><<<dim3(16, 2, DB), 256>>>(
        DT, 2 * DH, DS,
        p_probs, DS, (long long)DT * DS,
        enc, 2 * DH, (long long)DS * 2 * DH,
        p_ctx, 2 * DH, (long long)DT * 2 * DH, nullptr, 0);

    // pre = [trg | h_seq | ctx] @ W_pre^T : three accumulating GEMMs
    gemm_bf16<true><<<dim3(8, 128, 1), 256>>>(
        BT, DH, DE, trg, DE, 0, W_pre, 3328, 0,
        pre, DH, 0, nullptr, 0);
    gemm_bf16<true><<<dim3(8, 128, 1), 256>>>(
        BT, DH, DH, hseq, DH, 0, W_pre + DE, 3328, 0,
        pre, DH, 0, nullptr, 1);
    gemm_bf16<true><<<dim3(8, 128, 1), 256>>>(
        BT, DH, 2 * DH, p_ctx, 2 * DH, 0, W_pre + DE + DH, 3328, 0,
        pre, DH, 0, nullptr, 1);

    copy_hfinal<<<DB * DH / 256, 256>>>(hseq, hfin);
}

// round 12
// speedup vs baseline: 2.1757x; 1.3129x over previous
#include <cuda_runtime.h>
#include <cuda_bf16.h>
#include <math.h>

// Dims (fixed): B=64, T=256, S=256, E=256, H=1024
#define DB 64
#define DT 256
#define DS 256
#define DE 256
#define DH 1024

// ---- static scratch ----
__device__ float g_xgates[(size_t)DB * DT * 4 * DH]; // [B*T, 4H]
__device__ float g_projkey[(size_t)DB * DS * DH];    // [B*S, H]
__device__ float g_q[(size_t)DB * DT * DH];          // [B*T, H]
__device__ float g_probs[(size_t)DB * DT * DS];      // [B*T, S]
__device__ float g_ctx[(size_t)DB * DT * 2 * DH];    // [B*T, 2H]
__device__ float g_h0[DB * DH];
__device__ float g_c[DB * DH];
__device__ __nv_bfloat16 g_whi[(size_t)4 * DH * DH]; // W_hh split hi
__device__ __nv_bfloat16 g_wlo[(size_t)4 * DH * DH]; // W_hh split lo

__device__ __forceinline__ float tanh_f(float x) {
    float e = __expf(2.0f * x);
    return 1.0f - __fdividef(2.0f, e + 1.0f);
}
__device__ __forceinline__ float tanh_a(float x) {
    float y;
    asm("tanh.approx.f32 %0, %1;" : "=f"(y) : "f"(x));
    return y;
}
__device__ __forceinline__ float sigmoid_f(float x) {
    return __fdividef(1.0f, 1.0f + __expf(-x));
}

// split two floats into packed bf16x2 hi + lo words (elem0 in low half)
__device__ __forceinline__ void bf16_split2(float x0, float x1,
                                            unsigned& hi, unsigned& lo) {
    __nv_bfloat16 h0 = __float2bfloat16(x0), h1 = __float2bfloat16(x1);
    float r0 = x0 - __bfloat162float(h0);
    float r1 = x1 - __bfloat162float(h1);
    __nv_bfloat16 l0 = __float2bfloat16(r0), l1 = __float2bfloat16(r1);
    hi = ((unsigned)__bfloat16_as_ushort(h1) << 16) | __bfloat16_as_ushort(h0);
    lo = ((unsigned)__bfloat16_as_ushort(l1) << 16) | __bfloat16_as_ushort(l0);
}

#define MMA_BF16(d, a0, a1, a2, a3, b0, b1)                                   \
    asm volatile(                                                             \
        "mma.sync.aligned.m16n8k16.row.col.f32.bf16.bf16.f32 "                \
        "{%0,%1,%2,%3}, {%4,%5,%6,%7}, {%8,%9}, {%0,%1,%2,%3};"               \
        : "+f"(d[0]), "+f"(d[1]), "+f"(d[2]), "+f"(d[3])                      \
        : "r"(a0), "r"(a1), "r"(a2), "r"(a3), "r"(b0), "r"(b1))

__device__ __forceinline__ void ldsm4(unsigned& r0, unsigned& r1,
                                      unsigned& r2, unsigned& r3,
                                      const unsigned* p) {
    unsigned a = (unsigned)__cvta_generic_to_shared(p);
    asm volatile("ldmatrix.sync.aligned.m8n8.x4.shared.b16 {%0,%1,%2,%3}, [%4];"
                 : "=r"(r0), "=r"(r1), "=r"(r2), "=r"(r3) : "r"(a));
}

// one-time W_hh f32 -> bf16 hi/lo split
__global__ __launch_bounds__(256) void split_w(
    const float* __restrict__ W,
    __nv_bfloat16* __restrict__ whi, __nv_bfloat16* __restrict__ wlo)
{
    int i = blockIdx.x * 256 + threadIdx.x;
    float w = W[i];
    __nv_bfloat16 h = __float2bfloat16(w);
    whi[i] = h;
    wlo[i] = __float2bfloat16(w - __bfloat162float(h));
}

// ======================================================================
// bf16x3-split tensor-core GEMM with ldmatrix fragment loads.
// Block tile 128x128, BK=16, 256 threads (8 warps 2x4), warp tile 64x32.
// Smem layout: row-major, 12 words (24 bf16, 8 data + 4 pad) per row.
// ======================================================================
template <bool B_TRANS>
__global__ __launch_bounds__(256, 2) void gemm_bf16(
    int M, int N, int K,
    const float* __restrict__ A, int lda, long long sA,
    const float* __restrict__ Bm, int ldb, long long sB,
    float* __restrict__ C, int ldc, long long sC,
    const float* __restrict__ bias, int accumulate)
{
    __shared__ unsigned AhiS[2][128 * 12], AloS[2][128 * 12];
    __shared__ unsigned BhiS[2][128 * 12], BloS[2][128 * 12];

    const int bz = blockIdx.z;
    A += (long long)bz * sA;
    Bm += (long long)bz * sB;
    C += (long long)bz * sC;

    const int m0 = blockIdx.y * 128, n0 = blockIdx.x * 128;
    const int tid = threadIdx.x;
    const int wid = tid >> 5, lane = tid & 31;
    const int warp_m = wid >> 2, warp_n = wid & 3;
    const int tg = lane & 3, gr = lane >> 2;

    // ldmatrix lane decomposition
    const int lrow = ((lane >> 3) & 1) * 8 + (lane & 7); // A row-in-tile
    const int lka = (lane >> 4) * 4;                     // A k-word
    const int brow = (lane >> 4) * 8 + (lane & 7);       // B row-in-pair
    const int lkb = ((lane >> 3) & 1) * 4;               // B k-word

    // global loads: thread covers 8 k-floats of one row
    const int ar = tid >> 1;
    const int ac = (tid & 1) * 8;  // float offset
    const int aw = (tid & 1) * 4;  // word offset
    const float* Ag = A + (long long)(m0 + ar) * lda + ac;
    const float* Bg;
    int kp = 0, nn = 0;
    if (B_TRANS) {
        Bg = Bm + (long long)(n0 + ar) * ldb + ac;
    } else {
        kp = tid >> 5;           // k2-word 0..7
        nn = (tid & 31) * 4;     // n 0..124
        Bg = Bm + (long long)(2 * kp) * ldb + n0 + nn;
    }

    float acc[4][4][4];
#pragma unroll
    for (int i = 0; i < 4; i++)
#pragma unroll
        for (int j = 0; j < 4; j++)
#pragma unroll
            for (int c = 0; c < 4; c++) acc[i][j][c] = 0.0f;

    const int nk = K >> 4;
    float4 a0v, a1v, b0v, b1v;
    a0v = *(const float4*)Ag;
    a1v = *(const float4*)(Ag + 4);
    if (B_TRANS) {
        b0v = *(const float4*)Bg;
        b1v = *(const float4*)(Bg + 4);
    } else {
        b0v = *(const float4*)Bg;
        b1v = *(const float4*)(Bg + ldb);
    }

#define STORE_TILES(BUF)                                                      \
    {                                                                         \
        float va[8] = {a0v.x, a0v.y, a0v.z, a0v.w, a1v.x, a1v.y, a1v.z, a1v.w}; \
        unsigned h_[4], l_[4];                                                \
        _Pragma("unroll")                                                     \
        for (int j = 0; j < 4; j++)                                           \
            bf16_split2(va[2 * j], va[2 * j + 1], h_[j], l_[j]);              \
        *(uint4*)&AhiS[BUF][ar * 12 + aw] = make_uint4(h_[0], h_[1], h_[2], h_[3]); \
        *(uint4*)&AloS[BUF][ar * 12 + aw] = make_uint4(l_[0], l_[1], l_[2], l_[3]); \
        if (B_TRANS) {                                                        \
            float vb[8] = {b0v.x, b0v.y, b0v.z, b0v.w, b1v.x, b1v.y, b1v.z, b1v.w}; \
            _Pragma("unroll")                                                 \
            for (int j = 0; j < 4; j++)                                       \
                bf16_split2(vb[2 * j], vb[2 * j + 1], h_[j], l_[j]);          \
            *(uint4*)&BhiS[BUF][ar * 12 + aw] = make_uint4(h_[0], h_[1], h_[2], h_[3]); \
            *(uint4*)&BloS[BUF][ar * 12 + aw] = make_uint4(l_[0], l_[1], l_[2], l_[3]); \
        } else {                                                              \
            float r0[4] = {b0v.x, b0v.y, b0v.z, b0v.w};                       \
            float r1[4] = {b1v.x, b1v.y, b1v.z, b1v.w};                       \
            _Pragma("unroll")                                                 \
            for (int j = 0; j < 4; j++) {                                     \
                unsigned h, l;                                                \
                bf16_split2(r0[j], r1[j], h, l);                              \
                BhiS[BUF][(nn + j) * 12 + kp] = h;                            \
                BloS[BUF][(nn + j) * 12 + kp] = l;                            \
            }                                                                 \
        }                                                                     \
    }

    STORE_TILES(0);
    __syncthreads();

    int p = 0;
    for (int kt = 0; kt < nk; ++kt) {
        if (kt + 1 < nk) {
            const float* Agn = Ag + (long long)(kt + 1) * 16;
            a0v = *(const float4*)Agn;
            a1v = *(const float4*)(Agn + 4);
            if (B_TRANS) {
                const float* Bgn = Bg + (long long)(kt + 1) * 16;
                b0v = *(const float4*)Bgn;
                b1v = *(const float4*)(Bgn + 4);
            } else {
                const float* Bgn = Bg + (long long)(kt + 1) * 16 * ldb;
                b0v = *(const float4*)Bgn;
                b1v = *(const float4*)(Bgn + ldb);
            }
        }

        const unsigned* Ah = AhiS[p];
        const unsigned* Al = AloS[p];
        const unsigned* Bh = BhiS[p];
        const unsigned* Bl = BloS[p];

        unsigned bh[4][2], bl[4][2];
#pragma unroll
        for (int pr = 0; pr < 2; pr++) {
            int nb = warp_n * 32 + pr * 16;
            ldsm4(bh[2 * pr][0], bh[2 * pr][1], bh[2 * pr + 1][0], bh[2 * pr + 1][1],
                  &Bh[(nb + brow) * 12 + lkb]);
            ldsm4(bl[2 * pr][0], bl[2 * pr][1], bl[2 * pr + 1][0], bl[2 * pr + 1][1],
                  &Bl[(nb + brow) * 12 + lkb]);
        }
#pragma unroll
        for (int mt = 0; mt < 4; mt++) {
            int mb = warp_m * 64 + mt * 16;
            unsigned ah0, ah1, ah2, ah3, al0, al1, al2, al3;
            ldsm4(ah0, ah1, ah2, ah3, &Ah[(mb + lrow) * 12 + lka]);
            ldsm4(al0, al1, al2, al3, &Al[(mb + lrow) * 12 + lka]);
#pragma unroll
            for (int nt = 0; nt < 4; nt++) {
                MMA_BF16(acc[mt][nt], ah0, ah1, ah2, ah3, bh[nt][0], bh[nt][1]);
                MMA_BF16(acc[mt][nt], ah0, ah1, ah2, ah3, bl[nt][0], bl[nt][1]);
                MMA_BF16(acc[mt][nt], al0, al1, al2, al3, bh[nt][0], bh[nt][1]);
            }
        }

        if (kt + 1 < nk) STORE_TILES(p ^ 1);
        __syncthreads();
        p ^= 1;
    }
#undef STORE_TILES

#pragma unroll
    for (int mt = 0; mt < 4; mt++) {
        int gm0 = m0 + warp_m * 64 + mt * 16 + gr;
#pragma unroll
        for (int nt = 0; nt < 4; nt++) {
            int gn = n0 + warp_n * 32 + nt * 8 + tg * 2;
            float2 v0 = make_float2(acc[mt][nt][0], acc[mt][nt][1]);
            float2 v1 = make_float2(acc[mt][nt][2], acc[mt][nt][3]);
            if (bias) {
                float2 bb = *(const float2*)&bias[gn];
                v0.x += bb.x; v0.y += bb.y;
                v1.x += bb.x; v1.y += bb.y;
            }
            float* c0p = C + (long long)gm0 * ldc + gn;
            float* c1p = c0p + 8 * (long long)ldc;
            if (accumulate) {
                float2 o0 = *(const float2*)c0p;
                float2 o1 = *(const float2*)c1p;
                v0.x += o0.x; v0.y += o0.y;
                v1.x += o1.x; v1.y += o1.y;
            }
            *(float2*)c0p = v0;
            *(float2*)c1p = v1;
        }
    }
}

// ======================================================================
// Fused LSTM step: gates GEMM (bf16x3, pre-split W, ldmatrix) + cell.
// grid 128: block bi owns h in [bi*8, bi*8+8) for all 4 gates (32 W rows:
// wrow(bn) = (bn>>3)*1024 + h0 + (bn&7)). M=64, N=32, BK=32.
// 8 warps = 4(m) x 2(n), warp tile 16x16. Smem rows: 20-word stride.
// ======================================================================
__global__ __launch_bounds__(256) void lstm_fused(
    const float* __restrict__ hprev, int lda,
    const unsigned* __restrict__ Whi, const unsigned* __restrict__ Wlo,
    const float* __restrict__ xg_t, float* __restrict__ c,
    float* __restrict__ hout)
{
    __shared__ unsigned AhiS[2][64 * 20], AloS[2][64 * 20];
    __shared__ unsigned BhiS[2][32 * 20], BloS[2][32 * 20];
    __shared__ float Gs[64][40];

    const int h0 = blockIdx.x * 8;
    const int tid = threadIdx.x;
    const int wid = tid >> 5, lane = tid & 31;
    const int warp_m = wid >> 1, warp_n = wid & 1;
    const int tg = lane & 3, gr = lane >> 2;

    const int lrow = ((lane >> 3) & 1) * 8 + (lane & 7);
    const int lka = (lane >> 4) * 4;
    const int brow = (lane >> 4) * 8 + (lane & 7);
    const int lkb = ((lane >> 3) & 1) * 4;

    // A: row ar, 8 floats at ak
    const int ar = tid >> 2;          // 0..63
    const int ak = (tid & 3) * 8;     // float offset
    const int akw = (tid & 3) * 4;    // word offset
    const float* Ag = hprev + (long long)ar * lda + ak;
    // B: row bn (pre-split bf16 words), uint2 at bk2
    const int bn = tid >> 3;          // 0..31
    const int bk2 = (tid & 7) * 2;    // 0..14
    const int wrow = (bn >> 3) * 1024 + h0 + (bn & 7);
    const unsigned* BgH = Whi + ((long long)wrow << 9) + bk2;
    const unsigned* BgL = Wlo + ((long long)wrow << 9) + bk2;

    float acc[2][4];
#pragma unroll
    for (int i = 0; i < 2; i++)
#pragma unroll
        for (int j = 0; j < 4; j++) acc[i][j] = 0.0f;

    const int NK = DH / 32; // 32 tiles of BK=32
    float4 a0 = *(const float4*)Ag;
    float4 a1 = *(const float4*)(Ag + 4);
    uint2 bh2 = *(const uint2*)BgH;
    uint2 bl2 = *(const uint2*)BgL;

#define GS_STORE(BUF)                                                         \
    {                                                                         \
        float va[8] = {a0.x, a0.y, a0.z, a0.w, a1.x, a1.y, a1.z, a1.w};       \
        unsigned h_[4], l_[4];                                                \
        _Pragma("unroll")                                                     \
        for (int j = 0; j < 4; j++)                                           \
            bf16_split2(va[2 * j], va[2 * j + 1], h_[j], l_[j]);              \
        *(uint4*)&AhiS[BUF][ar * 20 + akw] = make_uint4(h_[0], h_[1], h_[2], h_[3]); \
        *(uint4*)&AloS[BUF][ar * 20 + akw] = make_uint4(l_[0], l_[1], l_[2], l_[3]); \
        *(uint2*)&BhiS[BUF][bn * 20 + bk2] = bh2;                             \
        *(uint2*)&BloS[BUF][bn * 20 + bk2] = bl2;                             \
    }

    GS_STORE(0);
    __syncthreads();

    int p = 0;
    for (int kt = 0; kt < NK; ++kt) {
        if (kt + 1 < NK) {
            const float* Agn = Ag + (kt + 1) * 32;
            a0 = *(const float4*)Agn;
            a1 = *(const float4*)(Agn + 4);
            bh2 = *(const uint2*)(BgH + (kt + 1) * 16);
            bl2 = *(const uint2*)(BgL + (kt + 1) * 16);
        }
        const unsigned* Ah = AhiS[p];
        const unsigned* Al = AloS[p];
        const unsigned* Bh = BhiS[p];
        const unsigned* Bl = BloS[p];
#pragma unroll
        for (int s = 0; s < 2; ++s) {
            unsigned b_h[2][2], b_l[2][2];
            int nb = warp_n * 16;
            ldsm4(b_h[0][0], b_h[0][1], b_h[1][0], b_h[1][1],
                  &Bh[(nb + brow) * 20 + s * 8 + lkb]);
            ldsm4(b_l[0][0], b_l[0][1], b_l[1][0], b_l[1][1],
                  &Bl[(nb + brow) * 20 + s * 8 + lkb]);
            int mb = warp_m * 16;
            unsigned ah0, ah1, ah2, ah3, al0, al1, al2, al3;
            ldsm4(ah0, ah1, ah2, ah3, &Ah[(mb + lrow) * 20 + s * 8 + lka]);
            ldsm4(al0, al1, al2, al3, &Al[(mb + lrow) * 20 + s * 8 + lka]);
#pragma unroll
            for (int nt = 0; nt < 2; nt++) {
                MMA_BF16(acc[nt], ah0, ah1, ah2, ah3, b_h[nt][0], b_h[nt][1]);
                MMA_BF16(acc[nt], ah0, ah1, ah2, ah3, b_l[nt][0], b_l[nt][1]);
                MMA_BF16(acc[nt], al0, al1, al2, al3, b_h[nt][0], b_h[nt][1]);
            }
        }
        if (kt + 1 < NK) GS_STORE(p ^ 1);
        __syncthreads();
        p ^= 1;
    }
#undef GS_STORE

    // gates -> smem
#pragma unroll
    for (int nt = 0; nt < 2; nt++) {
        int r0 = warp_m * 16 + gr;
        int cc = warp_n * 16 + nt * 8 + tg * 2;
        Gs[r0][cc] = acc[nt][0];
        Gs[r0][cc + 1] = acc[nt][1];
        Gs[r0 + 8][cc] = acc[nt][2];
        Gs[r0 + 8][cc + 1] = acc[nt][3];
    }
    __syncthreads();

    // fused pointwise cell: 512 outputs (64 b x 8 h)
#pragma unroll
    for (int j = 0; j < 2; j++) {
        int o = tid + j * 256;
        int b = o >> 3, hoff = o & 7;
        int h = h0 + hoff;
        const float* xg = xg_t + (long long)b * (DT * 4 * DH);
        float ig = Gs[b][hoff] + xg[h];
        float fg = Gs[b][8 + hoff] + xg[1024 + h];
        float gg = Gs[b][16 + hoff] + xg[2048 + h];
        float og = Gs[b][24 + hoff] + xg[3072 + h];
        float cv = sigmoid_f(fg) * c[b * DH + h] + sigmoid_f(ig) * tanh_f(gg);
        c[b * DH + h] = cv;
        hout[(long long)b * (DT * DH) + h] = sigmoid_f(og) * tanh_f(cv);
    }
}

// ======================================================================
// Small generic GEMM (bridge only): C = tanh(A*B^T + bias)
// ======================================================================
template <int TM, int TN>
__global__ __launch_bounds__(256) void gemm_small(
    int M, int N, int K,
    const float* __restrict__ A, int lda,
    const float* __restrict__ Bm, int ldb,
    float* __restrict__ C, int ldc,
    const float* __restrict__ bias)
{
    constexpr int BM = 16 * TM, BN = 16 * TN, BK = 16;
    __shared__ float As[BK][BM + 4];
    __shared__ float Bs[BK][BN + 4];
    int m0 = blockIdx.y * BM, n0 = blockIdx.x * BN;
    int tid = threadIdx.x;
    int rm = (tid / 16) * TM, rn = (tid % 16) * TN;
    float acc[TM][TN];
#pragma unroll
    for (int i = 0; i < TM; i++)
#pragma unroll
        for (int j = 0; j < TN; j++) acc[i][j] = 0.0f;
    for (int k0 = 0; k0 < K; k0 += BK) {
        for (int i = tid; i < BM * BK; i += 256) {
            int kk = i % BK, m = i / BK;
            int gm = m0 + m, gk = k0 + kk;
            As[kk][m] = (gm < M) ? A[(long long)gm * lda + gk] : 0.0f;
        }
        for (int i = tid; i < BN * BK; i += 256) {
            int kk = i % BK, n = i / BK;
            int gn = n0 + n, gk = k0 + kk;
            Bs[kk][n] = (gn < N) ? Bm[(long long)gn * ldb + gk] : 0.0f;
        }
        __syncthreads();
#pragma unroll
        for (int kk = 0; kk < BK; kk++) {
            float a[TM], bb[TN];
#pragma unroll
            for (int i = 0; i < TM; i++) a[i] = As[kk][rm + i];
#pragma unroll
            for (int j = 0; j < TN; j++) bb[j] = Bs[kk][rn + j];
#pragma unroll
            for (int i = 0; i < TM; i++)
#pragma unroll
                for (int j = 0; j < TN; j++) acc[i][j] += a[i] * bb[j];
        }
        __syncthreads();
    }
#pragma unroll
    for (int i = 0; i < TM; i++) {
        int gm = m0 + rm + i;
        if (gm >= M) continue;
#pragma unroll
        for (int j = 0; j < TN; j++) {
            int gn = n0 + rn + j;
            if (gn >= N) continue;
            C[(long long)gm * ldc + gn] = tanh_f(acc[i][j] + bias[gn]);
        }
    }
}

// energy[b,t,s] = sum_h tanh(q[b,t,h] + pk[b,s,h]) * v[h]  (mask all-true)
__global__ __launch_bounds__(256) void energy_kernel(
    const float* __restrict__ q, const float* __restrict__ pk,
    const float* __restrict__ v, float* __restrict__ out)
{
    int b = blockIdx.z;
    int t0 = blockIdx.y * 32, s0 = blockIdx.x * 32;
    __shared__ float Qs[32][33], Ps[32][33], Vs[32];
    int tid = threadIdx.x;
    int hh = tid & 31, r = tid >> 5;
    int tr = (tid / 16) * 2, sc = (tid % 16) * 2;
    const float* qb = q + ((long long)b * DT + t0) * DH;
    const float* pb = pk + ((long long)b * DS + s0) * DH;
    float a00 = 0, a01 = 0, a10 = 0, a11 = 0;

    for (int h0 = 0; h0 < DH; h0 += 32) {
#pragma unroll
        for (int rr = 0; rr < 4; rr++) {
            int row = r + rr * 8;
            Qs[hh][row] = qb[(long long)row * DH + h0 + hh];
            Ps[hh][row] = pb[(long long)row * DH + h0 + hh];
        }
        if (tid < 32) Vs[tid] = v[h0 + tid];
        __syncthreads();
#pragma unroll 8
        for (int k = 0; k < 32; k++) {
            float vv = Vs[k];
            float q0 = Qs[k][tr], q1 = Qs[k][tr + 1];
            float p0 = Ps[k][sc], p1 = Ps[k][sc + 1];
            a00 += tanh_a(q0 + p0) * vv;
            a01 += tanh_a(q0 + p1) * vv;
            a10 += tanh_a(q1 + p0) * vv;
            a11 += tanh_a(q1 + p1) * vv;
        }
        __syncthreads();
    }
    float* o0 = out + ((long long)b * DT + t0 + tr) * DS + s0 + sc;
    float* o1 = o0 + DS;
    o0[0] = a00; o0[1] = a01;
    o1[0] = a10; o1[1] = a11;
}

__global__ __launch_bounds__(256) void softmax_kernel(float* __restrict__ p)
{
    int row = blockIdx.x * 8 + (threadIdx.x >> 5);
    int lane = threadIdx.x & 31;
    float* pr = p + (long long)row * DS;
    float vals[8];
    float mx = -3.0e38f;
#pragma unroll
    for (int j = 0; j < 8; j++) { vals[j] = pr[lane + j * 32]; mx = fmaxf(mx, vals[j]); }
#pragma unroll
    for (int o = 16; o > 0; o >>= 1) mx = fmaxf(mx, __shfl_xor_sync(0xFFFFFFFFu, mx, o));
    float sum = 0.0f;
#pragma unroll
    for (int j = 0; j < 8; j++) { vals[j] = __expf(vals[j] - mx); sum += vals[j]; }
#pragma unroll
    for (int o = 16; o > 0; o >>= 1) sum += __shfl_xor_sync(0xFFFFFFFFu, sum, o);
    float inv = __fdividef(1.0f, sum);
#pragma unroll
    for (int j = 0; j < 8; j++) pr[lane + j * 32] = vals[j] * inv;
}

__global__ __launch_bounds__(256) void copy_hfinal(
    const float* __restrict__ hseq, float* __restrict__ out)
{
    int idx = blockIdx.x * 256 + threadIdx.x;
    int b = idx >> 10, h = idx & 1023;
    out[idx] = hseq[((long long)b * DT + (DT - 1)) * DH + h];
}

// ======================================================================
extern "C" void kernel_launch(void* const* d_in, const int* in_sizes, int n_in,
                              void* d_out, int out_size)
{
    const float* trg      = (const float*)d_in[0];
    const float* enc      = (const float*)d_in[1];
    const float* ehf      = (const float*)d_in[2];
    const float* ecf      = (const float*)d_in[3];
    const float* W_ih     = (const float*)d_in[6];
    const float* W_hh     = (const float*)d_in[7];
    const float* b_lstm   = (const float*)d_in[8];
    const float* W_bridge = (const float*)d_in[9];
    const float* b_bridge = (const float*)d_in[10];
    const float* W_key    = (const float*)d_in[11];
    const float* W_query  = (const float*)d_in[12];
    const float* v_energy = (const float*)d_in[13];
    const float* W_pre    = (const float*)d_in[14];

    float* out  = (float*)d_out;
    float* hseq = out;
    float* hfin = out + (long long)DB * DT * DH;
    float* pre  = hfin + (long long)DB * DH;

    float *p_xg, *p_pk, *p_q, *p_probs, *p_ctx, *p_h0, *p_c;
    __nv_bfloat16 *p_whi, *p_wlo;
    cudaGetSymbolAddress((void**)&p_xg, g_xgates);
    cudaGetSymbolAddress((void**)&p_pk, g_projkey);
    cudaGetSymbolAddress((void**)&p_q, g_q);
    cudaGetSymbolAddress((void**)&p_probs, g_probs);
    cudaGetSymbolAddress((void**)&p_ctx, g_ctx);
    cudaGetSymbolAddress((void**)&p_h0, g_h0);
    cudaGetSymbolAddress((void**)&p_c, g_c);
    cudaGetSymbolAddress((void**)&p_whi, g_whi);
    cudaGetSymbolAddress((void**)&p_wlo, g_wlo);

    const int BT = DB * DT; // 16384

    // One-time W_hh split (4M elems)
    split_w<<<(4 * DH * DH) / 256, 256>>>(W_hh, p_whi, p_wlo);

    // Bridge
    gemm_small<4, 2><<<dim3(DH / 32, 1, 1), 256>>>(
        DB, DH, 2 * DH, ehf, 2 * DH, W_bridge, 2 * DH, p_h0, DH, b_bridge);
    gemm_small<4, 2><<<dim3(DH / 32, 1, 1), 256>>>(
        DB, DH, 2 * DH, ecf, 2 * DH, W_bridge, 2 * DH, p_c, DH, b_bridge);

    // x_gates = trg @ W_ih^T + b_lstm : [16384, 4096] K=256
    gemm_bf16<true><<<dim3(32, 128, 1), 256>>>(
        BT, 4 * DH, DE, trg, DE, 0, W_ih, DE, 0,
        p_xg, 4 * DH, 0, b_lstm, 0);

    // proj_key = enc @ W_key^T : [16384, 1024] K=2048
    gemm_bf16<true><<<dim3(8, 128, 1), 256>>>(
        BT, DH, 2 * DH, enc, 2 * DH, 0, W_key, 2 * DH, 0,
        p_pk, DH, 0, nullptr, 0);

    // Sequential LSTM: single fused kernel per step
    for (int t = 0; t < DT; t++) {
        const float* hprev = (t == 0) ? p_h0 : (hseq + (long long)(t - 1) * DH);
        int lda = (t == 0) ? DH : (DT * DH);
        lstm_fused<<<128, 256>>>(hprev, lda,
                                 (const unsigned*)p_whi, (const unsigned*)p_wlo,
                                 p_xg + (long long)t * 4 * DH, p_c,
                                 hseq + (long long)t * DH);
    }

    // q = h_seq @ W_query^T : [16384, 1024] K=1024
    gemm_bf16<true><<<dim3(8, 128, 1), 256>>>(
        BT, DH, DH, hseq, DH, 0, W_query, DH, 0,
        p_q, DH, 0, nullptr, 0);

    // energy + softmax
    energy_kernel<<<dim3(DS / 32, DT / 32, DB), 256>>>(p_q, p_pk, v_energy, p_probs);
    softmax_kernel<<<BT / 8, 256>>>(p_probs);

    // ctx[b] = probs[b] @ enc[b] : batched NN [256,256]x[256,2048]
    gemm_bf16<false><<<dim3(16, 2, DB), 256>>>(
        DT, 2 * DH, DS,
        p_probs, DS, (long long)DT * DS,
        enc, 2 * DH, (long long)DS * 2 * DH,
        p_ctx, 2 * DH, (long long)DT * 2 * DH, nullptr, 0);

    // pre = [trg | h_seq | ctx] @ W_pre^T : three accumulating GEMMs
    gemm_bf16<true><<<dim3(8, 128, 1), 256>>>(
        BT, DH, DE, trg, DE, 0, W_pre, 3328, 0,
        pre, DH, 0, nullptr, 0);
    gemm_bf16<true><<<dim3(8, 128, 1), 256>>>(
        BT, DH, DH, hseq, DH, 0, W_pre + DE, 3328, 0,
        pre, DH, 0, nullptr, 1);
    gemm_bf16<true><<<dim3(8, 128, 1), 256>>>(
        BT, DH, 2 * DH, p_ctx, 2 * DH, 0, W_pre + DE + DH, 3328, 0,
        pre, DH, 0, nullptr, 1);

    copy_hfinal<<<DB * DH / 256, 256>>>(hseq, hfin);
}